// round 1
// baseline (speedup 1.0000x reference)
#include <cuda_runtime.h>
#include <math.h>

#define BSZ    2048
#define A_N    32
#define ROWS   (BSZ*A_N)        // 65536
#define HIDN   256
#define NHEAD  4
#define HDIM   16
#define CVDIM  16
#define TOPKN  8
#define NACT   20
#define NEGV   (-1e10f)
#define CCW    320              // concat width: 256 (h) + 64 (gated)

// ---------------- scratch (static device globals; no allocation) ------------
__device__ float g_X [(size_t)ROWS*HIDN];       // relu(fc1)
__device__ float g_GI[(size_t)ROWS*3*HIDN];     // x @ W_ih^T + b_ih
__device__ float g_GH[(size_t)ROWS*3*HIDN];     // h @ W_hh^T + b_hh
__device__ float g_CC[(size_t)ROWS*CCW];        // [h | gated] concat (p1 input)
__device__ float g_Q [(size_t)ROWS*64];
__device__ float g_K [(size_t)ROWS*64];
__device__ float g_V [(size_t)ROWS*64];
__device__ float g_GT[(size_t)ROWS*NHEAD];      // sigmoid gates
__device__ float g_P1[(size_t)ROWS*HIDN];       // relu(p1)

// ---------------- generic tiled SGEMM: C = A[M,K] @ W[N,K]^T + bias ---------
// BM=128 BN=64 BK=16, 256 threads, 8x4 per-thread microtile. ACT: 0 none, 1 relu.
template<int ACT>
__global__ void __launch_bounds__(256)
gemm_kernel(const float* __restrict__ A, int lda,
            const float* __restrict__ W,
            const float* __restrict__ bias,
            float* __restrict__ C, int ldc, int K)
{
    __shared__ float As[128][17];
    __shared__ float Ws[64][17];
    const int tid = threadIdx.x;
    const int tx  = tid & 15;          // N dir (x4)
    const int ty  = tid >> 4;          // M dir (x8)
    const int m0  = blockIdx.y * 128;
    const int n0  = blockIdx.x * 64;

    float acc[8][4];
    #pragma unroll
    for (int i = 0; i < 8; i++)
        #pragma unroll
        for (int j = 0; j < 4; j++) acc[i][j] = 0.f;

    const int lrow = tid >> 2;         // 0..63
    const int lcol = (tid & 3) << 2;   // 0,4,8,12

    for (int k0 = 0; k0 < K; k0 += 16) {
        #pragma unroll
        for (int r = 0; r < 2; r++) {
            float4 av = *(const float4*)(A + (size_t)(m0 + lrow + 64*r)*lda + k0 + lcol);
            As[lrow+64*r][lcol+0] = av.x; As[lrow+64*r][lcol+1] = av.y;
            As[lrow+64*r][lcol+2] = av.z; As[lrow+64*r][lcol+3] = av.w;
        }
        {
            float4 wv = *(const float4*)(W + (size_t)(n0 + lrow)*K + k0 + lcol);
            Ws[lrow][lcol+0] = wv.x; Ws[lrow][lcol+1] = wv.y;
            Ws[lrow][lcol+2] = wv.z; Ws[lrow][lcol+3] = wv.w;
        }
        __syncthreads();
        #pragma unroll
        for (int k = 0; k < 16; k++) {
            float a[8], w[4];
            #pragma unroll
            for (int i = 0; i < 8; i++) a[i] = As[ty*8+i][k];
            #pragma unroll
            for (int j = 0; j < 4; j++) w[j] = Ws[tx*4+j][k];
            #pragma unroll
            for (int i = 0; i < 8; i++)
                #pragma unroll
                for (int j = 0; j < 4; j++) acc[i][j] += a[i]*w[j];
        }
        __syncthreads();
    }
    #pragma unroll
    for (int i = 0; i < 8; i++) {
        const int m = m0 + ty*8 + i;
        #pragma unroll
        for (int j = 0; j < 4; j++) {
            const int n = n0 + tx*4 + j;
            float v = acc[i][j] + bias[n];
            if (ACT == 1) v = fmaxf(v, 0.f);
            C[(size_t)m*ldc + n] = v;
        }
    }
}

// ---------------- GRU elementwise: h = (1-z)*n + z*h_prev -------------------
__global__ void __launch_bounds__(256)
gru_kernel(const float* __restrict__ GI, const float* __restrict__ GH,
           const float* __restrict__ hin, float* __restrict__ cc,
           float* __restrict__ hout)
{
    size_t idx = (size_t)blockIdx.x*blockDim.x + threadIdx.x;
    if (idx >= (size_t)ROWS*HIDN) return;
    size_t row = idx >> 8;
    int j = (int)(idx & 255);
    size_t base = row*768 + j;
    float gir = GI[base], giz = GI[base+256], gin = GI[base+512];
    float ghr = GH[base], ghz = GH[base+256], ghn = GH[base+512];
    float r = 1.f/(1.f + expf(-(gir+ghr)));
    float z = 1.f/(1.f + expf(-(giz+ghz)));
    float n = tanhf(gin + r*ghn);
    float h = (1.f - z)*n + z*hin[idx];
    cc[row*CCW + j] = h;
    if (hout) hout[idx] = h;
}

// ---------------- head gates: sigmoid(h @ g_w^T + g_b), one warp per row ----
__global__ void __launch_bounds__(256)
gate_kernel(const float* __restrict__ CC, const float* __restrict__ gw,
            const float* __restrict__ gb, float* __restrict__ gate)
{
    int gwp  = (int)(((size_t)blockIdx.x*blockDim.x + threadIdx.x) >> 5);
    int lane = threadIdx.x & 31;
    if (gwp >= ROWS) return;
    int o = lane >> 3, part = lane & 7;
    const float* hr = CC + (size_t)gwp*CCW;
    const float* wr = gw + o*256;
    float s = 0.f;
    for (int k = part*4; k < 256; k += 32) {
        float4 hv = *(const float4*)(hr + k);
        float4 wv = *(const float4*)(wr + k);
        s += hv.x*wv.x + hv.y*wv.y + hv.z*wv.z + hv.w*wv.w;
    }
    s += __shfl_down_sync(0xffffffffu, s, 4, 8);
    s += __shfl_down_sync(0xffffffffu, s, 2, 8);
    s += __shfl_down_sync(0xffffffffu, s, 1, 8);
    if (part == 0) gate[(size_t)gwp*NHEAD + o] = 1.f/(1.f + expf(-(s + gb[o])));
}

// ---------------- per-batch sparse attention (one CTA per batch elem) -------
__global__ void __launch_bounds__(256)
attn_kernel(const float* __restrict__ Q, const float* __restrict__ K,
            const float* __restrict__ V, const float* __restrict__ gate,
            float* __restrict__ cc)
{
    __shared__ float QS[32][65], KS[32][65], VS[32][65];
    __shared__ float SS[4][32][33];          // [h][q][k]
    const int b   = blockIdx.x;
    const int tid = threadIdx.x;
    const float* Qb = Q + (size_t)b*2048;
    const float* Kb = K + (size_t)b*2048;
    const float* Vb = V + (size_t)b*2048;

    for (int i = tid; i < 2048; i += 256) {
        int r = i >> 6, c = i & 63;
        QS[r][c] = Qb[i]; KS[r][c] = Kb[i]; VS[r][c] = Vb[i];
    }
    __syncthreads();

    // scores: S[h][q][k] = 0.25 * <q,k>, diag = NEG
    for (int i = tid; i < 4096; i += 256) {
        int q = i >> 7, rem = i & 127;
        int h = rem >> 5, k = rem & 31;
        float s;
        if (q == k) s = NEGV;
        else {
            float acc = 0.f;
            #pragma unroll
            for (int d = 0; d < 16; d++) acc += QS[q][h*16+d]*KS[k][h*16+d];
            s = 0.25f*acc;
        }
        SS[h][q][k] = s;
    }
    __syncthreads();

    // top-8 (rank counting; ties measure-zero for random floats) + softmax
    if (tid < 128) {
        int h = tid >> 5, q = tid & 31;
        float v[32];
        #pragma unroll
        for (int k = 0; k < 32; k++) v[k] = SS[h][q][k];
        float maxv = -INFINITY;
        unsigned keep = 0u;
        #pragma unroll
        for (int k = 0; k < 32; k++) {
            int cnt = 0;
            #pragma unroll
            for (int j = 0; j < 32; j++) cnt += (v[j] > v[k]);
            if (cnt < TOPKN) { keep |= (1u << k); maxv = fmaxf(maxv, v[k]); }
        }
        float e[32], sum = 0.f;
        #pragma unroll
        for (int k = 0; k < 32; k++) {
            float ek = ((keep >> k) & 1u) ? expf(v[k] - maxv) : 0.f;
            e[k] = ek; sum += ek;
        }
        float inv = 1.f / sum;
        #pragma unroll
        for (int k = 0; k < 32; k++) SS[h][q][k] = e[k]*inv;
    }
    __syncthreads();

    // messages * gates -> concat[:,256:320]
    for (int i = tid; i < 2048; i += 256) {
        int q = i >> 6, hv = i & 63, h = hv >> 4;
        float acc = 0.f;
        #pragma unroll
        for (int k = 0; k < 32; k++) acc += SS[h][q][k]*VS[k][hv];
        float gt = gate[((size_t)b*32 + q)*NHEAD + h];
        cc[((size_t)b*32 + q)*CCW + 256 + hv] = acc*gt;
    }
}

// ---------------- p2 head: logits = P1 @ p2_w^T + p2_b (N=20) ---------------
__global__ void __launch_bounds__(256)
p2_kernel(const float* __restrict__ P1, const float* __restrict__ w,
          const float* __restrict__ b, float* __restrict__ out)
{
    __shared__ float WS[20*257];
    int tid = threadIdx.x;
    for (int i = tid; i < 20*256; i += 256) {
        int o = i >> 8, k = i & 255;
        WS[o*257 + k] = w[i];
    }
    __syncthreads();
    int r = tid / 20, o = tid % 20;           // 12 rows x 20 outs = 240 active
    int row = blockIdx.x*12 + r;
    if (tid >= 240 || row >= ROWS) return;
    const float* a  = P1 + (size_t)row*256;
    const float* wr = WS + o*257;
    float s = b[o];
    #pragma unroll 4
    for (int k = 0; k < 256; k += 4) {
        float4 av = *(const float4*)(a + k);
        s += av.x*wr[k] + av.y*wr[k+1] + av.z*wr[k+2] + av.w*wr[k+3];
    }
    out[(size_t)row*NACT + o] = s;
}

// ---------------------------------------------------------------------------
extern "C" void kernel_launch(void* const* d_in, const int* in_sizes, int n_in,
                              void* d_out, int out_size)
{
    const float* inputs = (const float*)d_in[0];
    const float* hidden = (const float*)d_in[1];
    const float* fc1_w  = (const float*)d_in[2];
    const float* fc1_b  = (const float*)d_in[3];
    const float* w_ih   = (const float*)d_in[4];
    const float* w_hh   = (const float*)d_in[5];
    const float* b_ih   = (const float*)d_in[6];
    const float* b_hh   = (const float*)d_in[7];
    const float* q_w    = (const float*)d_in[8];
    const float* q_b    = (const float*)d_in[9];
    const float* k_w    = (const float*)d_in[10];
    const float* k_b    = (const float*)d_in[11];
    const float* v_w    = (const float*)d_in[12];
    const float* v_b    = (const float*)d_in[13];
    const float* g_w    = (const float*)d_in[14];
    const float* g_b    = (const float*)d_in[15];
    const float* p1_w   = (const float*)d_in[16];
    const float* p1_b   = (const float*)d_in[17];
    const float* p2_w   = (const float*)d_in[18];
    const float* p2_b   = (const float*)d_in[19];

    float *X, *GI, *GH, *CC, *Q, *K, *V, *GT, *P1;
    cudaGetSymbolAddress((void**)&X,  g_X);
    cudaGetSymbolAddress((void**)&GI, g_GI);
    cudaGetSymbolAddress((void**)&GH, g_GH);
    cudaGetSymbolAddress((void**)&CC, g_CC);
    cudaGetSymbolAddress((void**)&Q,  g_Q);
    cudaGetSymbolAddress((void**)&K,  g_K);
    cudaGetSymbolAddress((void**)&V,  g_V);
    cudaGetSymbolAddress((void**)&GT, g_GT);
    cudaGetSymbolAddress((void**)&P1, g_P1);

    float* out  = (float*)d_out;
    float* hout = nullptr;
    long long need = (long long)ROWS*NACT + (long long)ROWS*HIDN;
    if ((long long)out_size >= need) hout = out + (size_t)ROWS*NACT;

    dim3 thr(256);

    // 1) x = relu(inputs @ fc1_w^T + fc1_b)
    gemm_kernel<1><<<dim3(256/64, ROWS/128), thr>>>(inputs, 256, fc1_w, fc1_b, X, 256, 256);
    // 2) gi = x @ W_ih^T + b_ih ; gh = h_in @ W_hh^T + b_hh
    gemm_kernel<0><<<dim3(768/64, ROWS/128), thr>>>(X,      256, w_ih, b_ih, GI, 768, 256);
    gemm_kernel<0><<<dim3(768/64, ROWS/128), thr>>>(hidden, 256, w_hh, b_hh, GH, 768, 256);
    // 3) GRU combine -> h (into concat[:, :256] and d_out h region)
    gru_kernel<<<ROWS, 256>>>(GI, GH, hidden, CC, hout);
    // 4) q/k/v projections (read h from concat, lda=320)
    gemm_kernel<0><<<dim3(1, ROWS/128), thr>>>(CC, CCW, q_w, q_b, Q, 64, 256);
    gemm_kernel<0><<<dim3(1, ROWS/128), thr>>>(CC, CCW, k_w, k_b, K, 64, 256);
    gemm_kernel<0><<<dim3(1, ROWS/128), thr>>>(CC, CCW, v_w, v_b, V, 64, 256);
    // 5) head gates
    gate_kernel<<<(ROWS*32)/256, 256>>>(CC, g_w, g_b, GT);
    // 6) sparse top-8 attention per batch element -> concat[:, 256:320]
    attn_kernel<<<BSZ, 256>>>(Q, K, V, GT, CC);
    // 7) p1 = relu(concat @ p1_w^T + p1_b)
    gemm_kernel<1><<<dim3(256/64, ROWS/128), thr>>>(CC, CCW, p1_w, p1_b, P1, 256, 320);
    // 8) logits = p1 @ p2_w^T + p2_b
    p2_kernel<<<(ROWS + 11)/12, 256>>>(P1, p2_w, p2_b, out);
}

// round 3
// speedup vs baseline: 1.1195x; 1.1195x over previous
#include <cuda_runtime.h>
#include <math.h>
#include <stdint.h>

#define BSZ    2048
#define A_N    32
#define ROWS   (BSZ*A_N)        // 65536
#define HIDN   256
#define NHEAD  4
#define HDIM   16
#define CVDIM  16
#define TOPKN  8
#define NACT   20
#define NEGV   (-1e10f)
#define CCW    320              // concat width: 256 (h) + 64 (gated)

// ---------------- scratch (static device globals; no allocation) ------------
__device__ float g_X [(size_t)ROWS*HIDN];       // relu(fc1)
__device__ float g_GI[(size_t)ROWS*3*HIDN];     // x @ W_ih^T + b_ih
__device__ float g_GH[(size_t)ROWS*3*HIDN];     // h @ W_hh^T + b_hh
__device__ float g_CC[(size_t)ROWS*CCW];        // [h | gated] concat (p1 input)
__device__ float g_Q [(size_t)ROWS*64];
__device__ float g_K [(size_t)ROWS*64];
__device__ float g_V [(size_t)ROWS*64];
__device__ float g_GT[(size_t)ROWS*NHEAD];      // sigmoid gates
__device__ float g_P1[(size_t)ROWS*HIDN];       // relu(p1)

// ---------------- tf32 helpers ----------------------------------------------
__device__ __forceinline__ uint32_t f2tf32(float x) {
    uint32_t y;
    asm("cvt.rna.tf32.f32 %0, %1;" : "=r"(y) : "f"(x));
    return y;
}

__device__ __forceinline__ void hilo(float x, uint32_t& hi, uint32_t& lo) {
    hi = f2tf32(x);
    lo = f2tf32(x - __uint_as_float(hi));
}

__device__ __forceinline__ void mma_tf32(float* d, const uint32_t* a, const uint32_t* b) {
    asm volatile(
        "mma.sync.aligned.m16n8k8.row.col.f32.tf32.tf32.f32 "
        "{%0,%1,%2,%3}, {%4,%5,%6,%7}, {%8,%9}, {%0,%1,%2,%3};"
        : "+f"(d[0]), "+f"(d[1]), "+f"(d[2]), "+f"(d[3])
        : "r"(a[0]), "r"(a[1]), "r"(a[2]), "r"(a[3]),
          "r"(b[0]), "r"(b[1]));
}

// ---------------- 3xTF32 tensor-core GEMM: C = A[M,K] @ W[N,K]^T + bias -----
// CTA tile 128x64, BK=32, 8 warps (warp tile 32x32). ACT: 0 none, 1 relu.
// Each operand split hi/lo; acc += aH*bL + aL*bH + aH*bH (3xTF32, ~fp32 prec).
// SMEM: row stride 32 words, col rotated by (row&7)*4 -> conflict-free frags.
template<int ACT>
__global__ void __launch_bounds__(256)
gemm_tf32x3(const float* __restrict__ A, int lda,
            const float* __restrict__ W,
            const float* __restrict__ bias,
            float* __restrict__ C, int ldc, int K)
{
    __shared__ uint32_t AsH[128][32];
    __shared__ uint32_t AsL[128][32];
    __shared__ uint32_t WsH[64][32];
    __shared__ uint32_t WsL[64][32];

    const int tid   = threadIdx.x;
    const int warp  = tid >> 5;
    const int lane  = tid & 31;
    const int group = lane >> 2;       // 0..7
    const int tig   = lane & 3;        // 0..3
    const int wm    = warp >> 1;       // 0..3 (m dir)
    const int wn    = warp & 1;        // 0..1 (n dir)
    const int m0    = blockIdx.y * 128;
    const int n0    = blockIdx.x * 64;

    float acc[2][4][4];
    #pragma unroll
    for (int mi = 0; mi < 2; mi++)
        #pragma unroll
        for (int ni = 0; ni < 4; ni++)
            #pragma unroll
            for (int j = 0; j < 4; j++) acc[mi][ni][j] = 0.f;

    for (int k0 = 0; k0 < K; k0 += 32) {
        // ---- load A tile 128x32 (4 float4 per thread), split hi/lo ----
        #pragma unroll
        for (int i = 0; i < 4; i++) {
            int f  = tid + i * 256;        // 0..1023
            int r  = f >> 3;
            int c4 = (f & 7) << 2;
            float4 v = *(const float4*)(A + (size_t)(m0 + r) * lda + k0 + c4);
            int rot = (r & 7) << 2;
            uint32_t h, l;
            hilo(v.x, h, l); AsH[r][(c4 + rot) & 31]     = h; AsL[r][(c4 + rot) & 31]     = l;
            hilo(v.y, h, l); AsH[r][(c4 + 1 + rot) & 31] = h; AsL[r][(c4 + 1 + rot) & 31] = l;
            hilo(v.z, h, l); AsH[r][(c4 + 2 + rot) & 31] = h; AsL[r][(c4 + 2 + rot) & 31] = l;
            hilo(v.w, h, l); AsH[r][(c4 + 3 + rot) & 31] = h; AsL[r][(c4 + 3 + rot) & 31] = l;
        }
        // ---- load W tile 64x32 (2 float4 per thread), split hi/lo ----
        #pragma unroll
        for (int i = 0; i < 2; i++) {
            int f  = tid + i * 256;        // 0..511
            int r  = f >> 3;
            int c4 = (f & 7) << 2;
            float4 v = *(const float4*)(W + (size_t)(n0 + r) * K + k0 + c4);
            int rot = (r & 7) << 2;
            uint32_t h, l;
            hilo(v.x, h, l); WsH[r][(c4 + rot) & 31]     = h; WsL[r][(c4 + rot) & 31]     = l;
            hilo(v.y, h, l); WsH[r][(c4 + 1 + rot) & 31] = h; WsL[r][(c4 + 1 + rot) & 31] = l;
            hilo(v.z, h, l); WsH[r][(c4 + 2 + rot) & 31] = h; WsL[r][(c4 + 2 + rot) & 31] = l;
            hilo(v.w, h, l); WsH[r][(c4 + 3 + rot) & 31] = h; WsL[r][(c4 + 3 + rot) & 31] = l;
        }
        __syncthreads();

        #pragma unroll
        for (int kk = 0; kk < 4; kk++) {
            const int rotg = group << 2;
            const int c0 = (kk * 8 + tig + rotg) & 31;
            const int c1 = (kk * 8 + tig + 4 + rotg) & 31;
            uint32_t aH[2][4], aL[2][4];
            #pragma unroll
            for (int mi = 0; mi < 2; mi++) {
                int row = wm * 32 + mi * 16 + group;
                aH[mi][0] = AsH[row][c0];     aL[mi][0] = AsL[row][c0];
                aH[mi][1] = AsH[row + 8][c0]; aL[mi][1] = AsL[row + 8][c0];
                aH[mi][2] = AsH[row][c1];     aL[mi][2] = AsL[row][c1];
                aH[mi][3] = AsH[row + 8][c1]; aL[mi][3] = AsL[row + 8][c1];
            }
            uint32_t bH[4][2], bL[4][2];
            #pragma unroll
            for (int ni = 0; ni < 4; ni++) {
                int rn = wn * 32 + ni * 8 + group;
                bH[ni][0] = WsH[rn][c0]; bL[ni][0] = WsL[rn][c0];
                bH[ni][1] = WsH[rn][c1]; bL[ni][1] = WsL[rn][c1];
            }
            #pragma unroll
            for (int mi = 0; mi < 2; mi++)
                #pragma unroll
                for (int ni = 0; ni < 4; ni++) {
                    mma_tf32(acc[mi][ni], aH[mi], bL[ni]);
                    mma_tf32(acc[mi][ni], aL[mi], bH[ni]);
                    mma_tf32(acc[mi][ni], aH[mi], bH[ni]);
                }
        }
        __syncthreads();
    }

    // ---- epilogue: bias (+relu), float2 stores ----
    #pragma unroll
    for (int mi = 0; mi < 2; mi++) {
        #pragma unroll
        for (int ni = 0; ni < 4; ni++) {
            int row = m0 + wm * 32 + mi * 16 + group;
            int col = n0 + wn * 32 + ni * 8 + 2 * tig;
            float b0 = bias[col], b1 = bias[col + 1];
            float v0 = acc[mi][ni][0] + b0;
            float v1 = acc[mi][ni][1] + b1;
            float v2 = acc[mi][ni][2] + b0;
            float v3 = acc[mi][ni][3] + b1;
            if (ACT == 1) {
                v0 = fmaxf(v0, 0.f); v1 = fmaxf(v1, 0.f);
                v2 = fmaxf(v2, 0.f); v3 = fmaxf(v3, 0.f);
            }
            *(float2*)(C + (size_t)row * ldc + col)       = make_float2(v0, v1);
            *(float2*)(C + (size_t)(row + 8) * ldc + col) = make_float2(v2, v3);
        }
    }
}

// ---------------- GRU elementwise: h = (1-z)*n + z*h_prev -------------------
__global__ void __launch_bounds__(256)
gru_kernel(const float* __restrict__ GI, const float* __restrict__ GH,
           const float* __restrict__ hin, float* __restrict__ cc,
           float* __restrict__ hout)
{
    size_t idx = (size_t)blockIdx.x*blockDim.x + threadIdx.x;
    if (idx >= (size_t)ROWS*HIDN) return;
    size_t row = idx >> 8;
    int j = (int)(idx & 255);
    size_t base = row*768 + j;
    float gir = GI[base], giz = GI[base+256], gin = GI[base+512];
    float ghr = GH[base], ghz = GH[base+256], ghn = GH[base+512];
    float r = 1.f/(1.f + expf(-(gir+ghr)));
    float z = 1.f/(1.f + expf(-(giz+ghz)));
    float n = tanhf(gin + r*ghn);
    float h = (1.f - z)*n + z*hin[idx];
    cc[row*CCW + j] = h;
    if (hout) hout[idx] = h;
}

// ---------------- head gates: sigmoid(h @ g_w^T + g_b), one warp per row ----
__global__ void __launch_bounds__(256)
gate_kernel(const float* __restrict__ CC, const float* __restrict__ gw,
            const float* __restrict__ gb, float* __restrict__ gate)
{
    int gwp  = (int)(((size_t)blockIdx.x*blockDim.x + threadIdx.x) >> 5);
    int lane = threadIdx.x & 31;
    if (gwp >= ROWS) return;
    int o = lane >> 3, part = lane & 7;
    const float* hr = CC + (size_t)gwp*CCW;
    const float* wr = gw + o*256;
    float s = 0.f;
    for (int k = part*4; k < 256; k += 32) {
        float4 hv = *(const float4*)(hr + k);
        float4 wv = *(const float4*)(wr + k);
        s += hv.x*wv.x + hv.y*wv.y + hv.z*wv.z + hv.w*wv.w;
    }
    s += __shfl_down_sync(0xffffffffu, s, 4, 8);
    s += __shfl_down_sync(0xffffffffu, s, 2, 8);
    s += __shfl_down_sync(0xffffffffu, s, 1, 8);
    if (part == 0) gate[(size_t)gwp*NHEAD + o] = 1.f/(1.f + expf(-(s + gb[o])));
}

// ---------------- per-batch sparse attention (one CTA per batch elem) -------
__global__ void __launch_bounds__(256)
attn_kernel(const float* __restrict__ Q, const float* __restrict__ K,
            const float* __restrict__ V, const float* __restrict__ gate,
            float* __restrict__ cc)
{
    __shared__ float QS[32][65], KS[32][65], VS[32][65];
    __shared__ float SS[4][32][33];          // [h][q][k]
    const int b   = blockIdx.x;
    const int tid = threadIdx.x;
    const float* Qb = Q + (size_t)b*2048;
    const float* Kb = K + (size_t)b*2048;
    const float* Vb = V + (size_t)b*2048;

    for (int i = tid; i < 2048; i += 256) {
        int r = i >> 6, c = i & 63;
        QS[r][c] = Qb[i]; KS[r][c] = Kb[i]; VS[r][c] = Vb[i];
    }
    __syncthreads();

    for (int i = tid; i < 4096; i += 256) {
        int q = i >> 7, rem = i & 127;
        int h = rem >> 5, k = rem & 31;
        float s;
        if (q == k) s = NEGV;
        else {
            float acc = 0.f;
            #pragma unroll
            for (int d = 0; d < 16; d++) acc += QS[q][h*16+d]*KS[k][h*16+d];
            s = 0.25f*acc;
        }
        SS[h][q][k] = s;
    }
    __syncthreads();

    if (tid < 128) {
        int h = tid >> 5, q = tid & 31;
        float v[32];
        #pragma unroll
        for (int k = 0; k < 32; k++) v[k] = SS[h][q][k];
        float maxv = -INFINITY;
        unsigned keep = 0u;
        #pragma unroll
        for (int k = 0; k < 32; k++) {
            int cnt = 0;
            #pragma unroll
            for (int j = 0; j < 32; j++) cnt += (v[j] > v[k]);
            if (cnt < TOPKN) { keep |= (1u << k); maxv = fmaxf(maxv, v[k]); }
        }
        float e[32], sum = 0.f;
        #pragma unroll
        for (int k = 0; k < 32; k++) {
            float ek = ((keep >> k) & 1u) ? expf(v[k] - maxv) : 0.f;
            e[k] = ek; sum += ek;
        }
        float inv = 1.f / sum;
        #pragma unroll
        for (int k = 0; k < 32; k++) SS[h][q][k] = e[k]*inv;
    }
    __syncthreads();

    for (int i = tid; i < 2048; i += 256) {
        int q = i >> 6, hv = i & 63, h = hv >> 4;
        float acc = 0.f;
        #pragma unroll
        for (int k = 0; k < 32; k++) acc += SS[h][q][k]*VS[k][hv];
        float gt = gate[((size_t)b*32 + q)*NHEAD + h];
        cc[((size_t)b*32 + q)*CCW + 256 + hv] = acc*gt;
    }
}

// ---------------- p2 head: logits = P1 @ p2_w^T + p2_b (N=20) ---------------
__global__ void __launch_bounds__(256)
p2_kernel(const float* __restrict__ P1, const float* __restrict__ w,
          const float* __restrict__ b, float* __restrict__ out)
{
    __shared__ float WS[20*257];
    int tid = threadIdx.x;
    for (int i = tid; i < 20*256; i += 256) {
        int o = i >> 8, k = i & 255;
        WS[o*257 + k] = w[i];
    }
    __syncthreads();
    int r = tid / 20, o = tid % 20;           // 12 rows x 20 outs = 240 active
    int row = blockIdx.x*12 + r;
    if (tid >= 240 || row >= ROWS) return;
    const float* a  = P1 + (size_t)row*256;
    const float* wr = WS + o*257;
    float s = b[o];
    #pragma unroll 4
    for (int k = 0; k < 256; k += 4) {
        float4 av = *(const float4*)(a + k);
        s += av.x*wr[k] + av.y*wr[k+1] + av.z*wr[k+2] + av.w*wr[k+3];
    }
    out[(size_t)row*NACT + o] = s;
}

// ---------------------------------------------------------------------------
extern "C" void kernel_launch(void* const* d_in, const int* in_sizes, int n_in,
                              void* d_out, int out_size)
{
    const float* inputs = (const float*)d_in[0];
    const float* hidden = (const float*)d_in[1];
    const float* fc1_w  = (const float*)d_in[2];
    const float* fc1_b  = (const float*)d_in[3];
    const float* w_ih   = (const float*)d_in[4];
    const float* w_hh   = (const float*)d_in[5];
    const float* b_ih   = (const float*)d_in[6];
    const float* b_hh   = (const float*)d_in[7];
    const float* q_w    = (const float*)d_in[8];
    const float* q_b    = (const float*)d_in[9];
    const float* k_w    = (const float*)d_in[10];
    const float* k_b    = (const float*)d_in[11];
    const float* v_w    = (const float*)d_in[12];
    const float* v_b    = (const float*)d_in[13];
    const float* g_w    = (const float*)d_in[14];
    const float* g_b    = (const float*)d_in[15];
    const float* p1_w   = (const float*)d_in[16];
    const float* p1_b   = (const float*)d_in[17];
    const float* p2_w   = (const float*)d_in[18];
    const float* p2_b   = (const float*)d_in[19];

    float *X, *GI, *GH, *CC, *Q, *K, *V, *GT, *P1;
    cudaGetSymbolAddress((void**)&X,  g_X);
    cudaGetSymbolAddress((void**)&GI, g_GI);
    cudaGetSymbolAddress((void**)&GH, g_GH);
    cudaGetSymbolAddress((void**)&CC, g_CC);
    cudaGetSymbolAddress((void**)&Q,  g_Q);
    cudaGetSymbolAddress((void**)&K,  g_K);
    cudaGetSymbolAddress((void**)&V,  g_V);
    cudaGetSymbolAddress((void**)&GT, g_GT);
    cudaGetSymbolAddress((void**)&P1, g_P1);

    float* out  = (float*)d_out;
    float* hout = nullptr;
    long long need = (long long)ROWS*NACT + (long long)ROWS*HIDN;
    if ((long long)out_size >= need) hout = out + (size_t)ROWS*NACT;

    dim3 thr(256);

    // 1) x = relu(inputs @ fc1_w^T + fc1_b)
    gemm_tf32x3<1><<<dim3(256/64, ROWS/128), thr>>>(inputs, 256, fc1_w, fc1_b, X, 256, 256);
    // 2) gi = x @ W_ih^T + b_ih ; gh = h_in @ W_hh^T + b_hh
    gemm_tf32x3<0><<<dim3(768/64, ROWS/128), thr>>>(X,      256, w_ih, b_ih, GI, 768, 256);
    gemm_tf32x3<0><<<dim3(768/64, ROWS/128), thr>>>(hidden, 256, w_hh, b_hh, GH, 768, 256);
    // 3) GRU combine -> h (into concat[:, :256] and d_out h region)
    gru_kernel<<<ROWS, 256>>>(GI, GH, hidden, CC, hout);
    // 4) q/k/v projections (read h from concat, lda=320)
    gemm_tf32x3<0><<<dim3(1, ROWS/128), thr>>>(CC, CCW, q_w, q_b, Q, 64, 256);
    gemm_tf32x3<0><<<dim3(1, ROWS/128), thr>>>(CC, CCW, k_w, k_b, K, 64, 256);
    gemm_tf32x3<0><<<dim3(1, ROWS/128), thr>>>(CC, CCW, v_w, v_b, V, 64, 256);
    // 5) head gates
    gate_kernel<<<(ROWS*32)/256, 256>>>(CC, g_w, g_b, GT);
    // 6) sparse top-8 attention per batch element -> concat[:, 256:320]
    attn_kernel<<<BSZ, 256>>>(Q, K, V, GT, CC);
    // 7) p1 = relu(concat @ p1_w^T + p1_b)
    gemm_tf32x3<1><<<dim3(256/64, ROWS/128), thr>>>(CC, CCW, p1_w, p1_b, P1, 256, 320);
    // 8) logits = p1 @ p2_w^T + p2_b
    p2_kernel<<<(ROWS + 11)/12, 256>>>(P1, p2_w, p2_b, out);
}

// round 4
// speedup vs baseline: 1.9692x; 1.7590x over previous
#include <cuda_runtime.h>
#include <cuda_bf16.h>
#include <math.h>
#include <stdint.h>

#define BSZ    2048
#define A_N    32
#define ROWS   (BSZ*A_N)        // 65536
#define HIDN   256
#define NHEAD  4
#define HDIM   16
#define CVDIM  16
#define TOPKN  8
#define NACT   20
#define NEGV   (-1e10f)
#define CCW    320              // concat width: 256 (h) + 64 (gated)

// ---------------- scratch (static device globals; no allocation) ------------
__device__ float g_X [(size_t)ROWS*HIDN];       // relu(fc1)
__device__ float g_GI[(size_t)ROWS*3*HIDN];     // x @ W_ih^T + b_ih
__device__ float g_GH[(size_t)ROWS*3*HIDN];     // h @ W_hh^T + b_hh
__device__ float g_CC[(size_t)ROWS*CCW];        // [h | gated] concat (p1 input)
__device__ float g_Q [(size_t)ROWS*64];
__device__ float g_K [(size_t)ROWS*64];
__device__ float g_V [(size_t)ROWS*64];
__device__ float g_GT[(size_t)ROWS*NHEAD];      // sigmoid gates
__device__ float g_P1[(size_t)ROWS*HIDN];       // relu(p1)

// ---------------- bf16 split helpers ----------------------------------------
// hi = bf16(x); lo = bf16(x - hi). Two packed words for (x0,x1).
__device__ __forceinline__ void split2(float x0, float x1, uint32_t& wh, uint32_t& wl) {
    __nv_bfloat16 h0 = __float2bfloat16_rn(x0);
    __nv_bfloat16 h1 = __float2bfloat16_rn(x1);
    __nv_bfloat16 l0 = __float2bfloat16_rn(x0 - __bfloat162float(h0));
    __nv_bfloat16 l1 = __float2bfloat16_rn(x1 - __bfloat162float(h1));
    __nv_bfloat162 H = __nv_bfloat162(h0, h1);
    __nv_bfloat162 L = __nv_bfloat162(l0, l1);
    wh = *reinterpret_cast<uint32_t*>(&H);
    wl = *reinterpret_cast<uint32_t*>(&L);
}

__device__ __forceinline__ void mma_bf16(float* d, const uint32_t* a, const uint32_t* b) {
    asm volatile(
        "mma.sync.aligned.m16n8k16.row.col.f32.bf16.bf16.f32 "
        "{%0,%1,%2,%3}, {%4,%5,%6,%7}, {%8,%9}, {%0,%1,%2,%3};"
        : "+f"(d[0]), "+f"(d[1]), "+f"(d[2]), "+f"(d[3])
        : "r"(a[0]), "r"(a[1]), "r"(a[2]), "r"(a[3]),
          "r"(b[0]), "r"(b[1]));
}

// ---------------- 3xBF16 tensor-core GEMM: C = A[M,K] @ W[N,K]^T + bias -----
// CTA tile 128x64, BK=32 (2 x k16 MMA steps), 8 warps (warp tile 32x32).
// Operands split hi/lo bf16; acc += aH*bL + aL*bH + aH*bH (~16-17 bit operands).
// SMEM word stride 20 -> conflict-free fragment loads ((20g+w) mod 32 distinct).
template<int ACT>
__global__ void __launch_bounds__(256)
gemm_bf16x3(const float* __restrict__ A, int lda,
            const float* __restrict__ W,
            const float* __restrict__ bias,
            float* __restrict__ C, int ldc, int K)
{
    __shared__ uint32_t AsH[128][20];
    __shared__ uint32_t AsL[128][20];
    __shared__ uint32_t WsH[64][20];
    __shared__ uint32_t WsL[64][20];

    const int tid   = threadIdx.x;
    const int warp  = tid >> 5;
    const int lane  = tid & 31;
    const int group = lane >> 2;       // 0..7
    const int tig   = lane & 3;        // 0..3
    const int wm    = warp >> 1;       // 0..3 (m dir)
    const int wn    = warp & 1;        // 0..1 (n dir)
    const int m0    = blockIdx.y * 128;
    const int n0    = blockIdx.x * 64;

    float acc[2][4][4];
    #pragma unroll
    for (int mi = 0; mi < 2; mi++)
        #pragma unroll
        for (int ni = 0; ni < 4; ni++)
            #pragma unroll
            for (int j = 0; j < 4; j++) acc[mi][ni][j] = 0.f;

    for (int k0 = 0; k0 < K; k0 += 32) {
        // ---- A tile 128x32 floats: 4 float4 per thread, split+pack ----
        #pragma unroll
        for (int i = 0; i < 4; i++) {
            int f  = tid + i * 256;        // 0..1023
            int r  = f >> 3;
            int c4 = (f & 7) << 2;         // float col (0,4,..,28)
            float4 v = *(const float4*)(A + (size_t)(m0 + r) * lda + k0 + c4);
            int w = c4 >> 1;               // word col (0,2,..,14)
            uint32_t h0, l0, h1, l1;
            split2(v.x, v.y, h0, l0);
            split2(v.z, v.w, h1, l1);
            AsH[r][w] = h0; AsH[r][w + 1] = h1;
            AsL[r][w] = l0; AsL[r][w + 1] = l1;
        }
        // ---- W tile 64x32 floats: 2 float4 per thread ----
        #pragma unroll
        for (int i = 0; i < 2; i++) {
            int f  = tid + i * 256;        // 0..511
            int r  = f >> 3;
            int c4 = (f & 7) << 2;
            float4 v = *(const float4*)(W + (size_t)(n0 + r) * K + k0 + c4);
            int w = c4 >> 1;
            uint32_t h0, l0, h1, l1;
            split2(v.x, v.y, h0, l0);
            split2(v.z, v.w, h1, l1);
            WsH[r][w] = h0; WsH[r][w + 1] = h1;
            WsL[r][w] = l0; WsL[r][w + 1] = l1;
        }
        __syncthreads();

        #pragma unroll
        for (int kk = 0; kk < 2; kk++) {
            const int w0 = kk * 8 + tig;
            const int w1 = w0 + 4;
            uint32_t aH[2][4], aL[2][4];
            #pragma unroll
            for (int mi = 0; mi < 2; mi++) {
                int row = wm * 32 + mi * 16 + group;
                aH[mi][0] = AsH[row][w0];     aL[mi][0] = AsL[row][w0];
                aH[mi][1] = AsH[row + 8][w0]; aL[mi][1] = AsL[row + 8][w0];
                aH[mi][2] = AsH[row][w1];     aL[mi][2] = AsL[row][w1];
                aH[mi][3] = AsH[row + 8][w1]; aL[mi][3] = AsL[row + 8][w1];
            }
            uint32_t bH[4][2], bL[4][2];
            #pragma unroll
            for (int ni = 0; ni < 4; ni++) {
                int rn = wn * 32 + ni * 8 + group;
                bH[ni][0] = WsH[rn][w0]; bL[ni][0] = WsL[rn][w0];
                bH[ni][1] = WsH[rn][w1]; bL[ni][1] = WsL[rn][w1];
            }
            #pragma unroll
            for (int mi = 0; mi < 2; mi++)
                #pragma unroll
                for (int ni = 0; ni < 4; ni++) {
                    mma_bf16(acc[mi][ni], aH[mi], bL[ni]);
                    mma_bf16(acc[mi][ni], aL[mi], bH[ni]);
                    mma_bf16(acc[mi][ni], aH[mi], bH[ni]);
                }
        }
        __syncthreads();
    }

    // ---- epilogue: bias (+relu), float2 stores ----
    #pragma unroll
    for (int mi = 0; mi < 2; mi++) {
        #pragma unroll
        for (int ni = 0; ni < 4; ni++) {
            int row = m0 + wm * 32 + mi * 16 + group;
            int col = n0 + wn * 32 + ni * 8 + 2 * tig;
            float b0 = bias[col], b1 = bias[col + 1];
            float v0 = acc[mi][ni][0] + b0;
            float v1 = acc[mi][ni][1] + b1;
            float v2 = acc[mi][ni][2] + b0;
            float v3 = acc[mi][ni][3] + b1;
            if (ACT == 1) {
                v0 = fmaxf(v0, 0.f); v1 = fmaxf(v1, 0.f);
                v2 = fmaxf(v2, 0.f); v3 = fmaxf(v3, 0.f);
            }
            *(float2*)(C + (size_t)row * ldc + col)       = make_float2(v0, v1);
            *(float2*)(C + (size_t)(row + 8) * ldc + col) = make_float2(v2, v3);
        }
    }
}

// ---------------- GRU elementwise: h = (1-z)*n + z*h_prev -------------------
__global__ void __launch_bounds__(256)
gru_kernel(const float* __restrict__ GI, const float* __restrict__ GH,
           const float* __restrict__ hin, float* __restrict__ cc,
           float* __restrict__ hout)
{
    size_t idx = (size_t)blockIdx.x*blockDim.x + threadIdx.x;
    if (idx >= (size_t)ROWS*HIDN) return;
    size_t row = idx >> 8;
    int j = (int)(idx & 255);
    size_t base = row*768 + j;
    float gir = GI[base], giz = GI[base+256], gin = GI[base+512];
    float ghr = GH[base], ghz = GH[base+256], ghn = GH[base+512];
    float r = 1.f/(1.f + expf(-(gir+ghr)));
    float z = 1.f/(1.f + expf(-(giz+ghz)));
    float n = tanhf(gin + r*ghn);
    float h = (1.f - z)*n + z*hin[idx];
    cc[row*CCW + j] = h;
    if (hout) hout[idx] = h;
}

// ---------------- head gates: sigmoid(h @ g_w^T + g_b), one warp per row ----
__global__ void __launch_bounds__(256)
gate_kernel(const float* __restrict__ CC, const float* __restrict__ gw,
            const float* __restrict__ gb, float* __restrict__ gate)
{
    int gwp  = (int)(((size_t)blockIdx.x*blockDim.x + threadIdx.x) >> 5);
    int lane = threadIdx.x & 31;
    if (gwp >= ROWS) return;
    int o = lane >> 3, part = lane & 7;
    const float* hr = CC + (size_t)gwp*CCW;
    const float* wr = gw + o*256;
    float s = 0.f;
    for (int k = part*4; k < 256; k += 32) {
        float4 hv = *(const float4*)(hr + k);
        float4 wv = *(const float4*)(wr + k);
        s += hv.x*wv.x + hv.y*wv.y + hv.z*wv.z + hv.w*wv.w;
    }
    s += __shfl_down_sync(0xffffffffu, s, 4, 8);
    s += __shfl_down_sync(0xffffffffu, s, 2, 8);
    s += __shfl_down_sync(0xffffffffu, s, 1, 8);
    if (part == 0) gate[(size_t)gwp*NHEAD + o] = 1.f/(1.f + expf(-(s + gb[o])));
}

// ---------------- per-batch sparse attention (one CTA per batch elem) -------
__global__ void __launch_bounds__(256)
attn_kernel(const float* __restrict__ Q, const float* __restrict__ K,
            const float* __restrict__ V, const float* __restrict__ gate,
            float* __restrict__ cc)
{
    __shared__ float QS[32][65], KS[32][65], VS[32][65];
    __shared__ float SS[4][32][33];          // [h][q][k]
    const int b   = blockIdx.x;
    const int tid = threadIdx.x;
    const float* Qb = Q + (size_t)b*2048;
    const float* Kb = K + (size_t)b*2048;
    const float* Vb = V + (size_t)b*2048;

    for (int i = tid; i < 2048; i += 256) {
        int r = i >> 6, c = i & 63;
        QS[r][c] = Qb[i]; KS[r][c] = Kb[i]; VS[r][c] = Vb[i];
    }
    __syncthreads();

    for (int i = tid; i < 4096; i += 256) {
        int q = i >> 7, rem = i & 127;
        int h = rem >> 5, k = rem & 31;
        float s;
        if (q == k) s = NEGV;
        else {
            float acc = 0.f;
            #pragma unroll
            for (int d = 0; d < 16; d++) acc += QS[q][h*16+d]*KS[k][h*16+d];
            s = 0.25f*acc;
        }
        SS[h][q][k] = s;
    }
    __syncthreads();

    if (tid < 128) {
        int h = tid >> 5, q = tid & 31;
        float v[32];
        #pragma unroll
        for (int k = 0; k < 32; k++) v[k] = SS[h][q][k];
        float maxv = -INFINITY;
        unsigned keep = 0u;
        #pragma unroll
        for (int k = 0; k < 32; k++) {
            int cnt = 0;
            #pragma unroll
            for (int j = 0; j < 32; j++) cnt += (v[j] > v[k]);
            if (cnt < TOPKN) { keep |= (1u << k); maxv = fmaxf(maxv, v[k]); }
        }
        float e[32], sum = 0.f;
        #pragma unroll
        for (int k = 0; k < 32; k++) {
            float ek = ((keep >> k) & 1u) ? expf(v[k] - maxv) : 0.f;
            e[k] = ek; sum += ek;
        }
        float inv = 1.f / sum;
        #pragma unroll
        for (int k = 0; k < 32; k++) SS[h][q][k] = e[k]*inv;
    }
    __syncthreads();

    for (int i = tid; i < 2048; i += 256) {
        int q = i >> 6, hv = i & 63, h = hv >> 4;
        float acc = 0.f;
        #pragma unroll
        for (int k = 0; k < 32; k++) acc += SS[h][q][k]*VS[k][hv];
        float gt = gate[((size_t)b*32 + q)*NHEAD + h];
        cc[((size_t)b*32 + q)*CCW + 256 + hv] = acc*gt;
    }
}

// ---------------- p2 head: logits = P1 @ p2_w^T + p2_b (N=20) ---------------
__global__ void __launch_bounds__(256)
p2_kernel(const float* __restrict__ P1, const float* __restrict__ w,
          const float* __restrict__ b, float* __restrict__ out)
{
    __shared__ float WS[20*257];
    int tid = threadIdx.x;
    for (int i = tid; i < 20*256; i += 256) {
        int o = i >> 8, k = i & 255;
        WS[o*257 + k] = w[i];
    }
    __syncthreads();
    int r = tid / 20, o = tid % 20;           // 12 rows x 20 outs = 240 active
    int row = blockIdx.x*12 + r;
    if (tid >= 240 || row >= ROWS) return;
    const float* a  = P1 + (size_t)row*256;
    const float* wr = WS + o*257;
    float s = b[o];
    #pragma unroll 4
    for (int k = 0; k < 256; k += 4) {
        float4 av = *(const float4*)(a + k);
        s += av.x*wr[k] + av.y*wr[k+1] + av.z*wr[k+2] + av.w*wr[k+3];
    }
    out[(size_t)row*NACT + o] = s;
}

// ---------------------------------------------------------------------------
extern "C" void kernel_launch(void* const* d_in, const int* in_sizes, int n_in,
                              void* d_out, int out_size)
{
    const float* inputs = (const float*)d_in[0];
    const float* hidden = (const float*)d_in[1];
    const float* fc1_w  = (const float*)d_in[2];
    const float* fc1_b  = (const float*)d_in[3];
    const float* w_ih   = (const float*)d_in[4];
    const float* w_hh   = (const float*)d_in[5];
    const float* b_ih   = (const float*)d_in[6];
    const float* b_hh   = (const float*)d_in[7];
    const float* q_w    = (const float*)d_in[8];
    const float* q_b    = (const float*)d_in[9];
    const float* k_w    = (const float*)d_in[10];
    const float* k_b    = (const float*)d_in[11];
    const float* v_w    = (const float*)d_in[12];
    const float* v_b    = (const float*)d_in[13];
    const float* g_w    = (const float*)d_in[14];
    const float* g_b    = (const float*)d_in[15];
    const float* p1_w   = (const float*)d_in[16];
    const float* p1_b   = (const float*)d_in[17];
    const float* p2_w   = (const float*)d_in[18];
    const float* p2_b   = (const float*)d_in[19];

    float *X, *GI, *GH, *CC, *Q, *K, *V, *GT, *P1;
    cudaGetSymbolAddress((void**)&X,  g_X);
    cudaGetSymbolAddress((void**)&GI, g_GI);
    cudaGetSymbolAddress((void**)&GH, g_GH);
    cudaGetSymbolAddress((void**)&CC, g_CC);
    cudaGetSymbolAddress((void**)&Q,  g_Q);
    cudaGetSymbolAddress((void**)&K,  g_K);
    cudaGetSymbolAddress((void**)&V,  g_V);
    cudaGetSymbolAddress((void**)&GT, g_GT);
    cudaGetSymbolAddress((void**)&P1, g_P1);

    float* out  = (float*)d_out;
    float* hout = nullptr;
    long long need = (long long)ROWS*NACT + (long long)ROWS*HIDN;
    if ((long long)out_size >= need) hout = out + (size_t)ROWS*NACT;

    dim3 thr(256);

    // 1) x = relu(inputs @ fc1_w^T + fc1_b)
    gemm_bf16x3<1><<<dim3(256/64, ROWS/128), thr>>>(inputs, 256, fc1_w, fc1_b, X, 256, 256);
    // 2) gi = x @ W_ih^T + b_ih ; gh = h_in @ W_hh^T + b_hh
    gemm_bf16x3<0><<<dim3(768/64, ROWS/128), thr>>>(X,      256, w_ih, b_ih, GI, 768, 256);
    gemm_bf16x3<0><<<dim3(768/64, ROWS/128), thr>>>(hidden, 256, w_hh, b_hh, GH, 768, 256);
    // 3) GRU combine -> h (into concat[:, :256] and d_out h region)
    gru_kernel<<<ROWS, 256>>>(GI, GH, hidden, CC, hout);
    // 4) q/k/v projections (read h from concat, lda=320)
    gemm_bf16x3<0><<<dim3(1, ROWS/128), thr>>>(CC, CCW, q_w, q_b, Q, 64, 256);
    gemm_bf16x3<0><<<dim3(1, ROWS/128), thr>>>(CC, CCW, k_w, k_b, K, 64, 256);
    gemm_bf16x3<0><<<dim3(1, ROWS/128), thr>>>(CC, CCW, v_w, v_b, V, 64, 256);
    // 5) head gates
    gate_kernel<<<(ROWS*32)/256, 256>>>(CC, g_w, g_b, GT);
    // 6) sparse top-8 attention per batch element -> concat[:, 256:320]
    attn_kernel<<<BSZ, 256>>>(Q, K, V, GT, CC);
    // 7) p1 = relu(concat @ p1_w^T + p1_b)
    gemm_bf16x3<1><<<dim3(256/64, ROWS/128), thr>>>(CC, CCW, p1_w, p1_b, P1, 256, 320);
    // 8) logits = p1 @ p2_w^T + p2_b
    p2_kernel<<<(ROWS + 11)/12, 256>>>(P1, p2_w, p2_b, out);
}

// round 5
// speedup vs baseline: 2.0462x; 1.0391x over previous
#include <cuda_runtime.h>
#include <cuda_bf16.h>
#include <math.h>
#include <stdint.h>

#define BSZ    2048
#define A_N    32
#define ROWS   (BSZ*A_N)        // 65536
#define HIDN   256
#define NHEAD  4
#define TOPKN  8
#define NACT   20
#define NEGV   (-1e10f)
#define CCW    320              // concat width: 256 (h) + 64 (gated)

// ---------------- scratch (static device globals; no allocation) ------------
__device__ float g_X [(size_t)ROWS*HIDN];       // relu(fc1)
__device__ float g_GI[(size_t)ROWS*3*HIDN];     // x @ W_ih^T + b_ih
__device__ float g_CC[(size_t)ROWS*CCW];        // [h | gated] concat (p1 input)
__device__ float g_Q [(size_t)ROWS*64];
__device__ float g_K [(size_t)ROWS*64];
__device__ float g_V [(size_t)ROWS*64];
__device__ float g_GT[(size_t)ROWS*NHEAD];      // sigmoid gates
__device__ float g_P1[(size_t)ROWS*HIDN];       // relu(p1)

// ---------------- bf16 split helpers ----------------------------------------
__device__ __forceinline__ void split2(float x0, float x1, uint32_t& wh, uint32_t& wl) {
    __nv_bfloat16 h0 = __float2bfloat16_rn(x0);
    __nv_bfloat16 h1 = __float2bfloat16_rn(x1);
    __nv_bfloat16 l0 = __float2bfloat16_rn(x0 - __bfloat162float(h0));
    __nv_bfloat16 l1 = __float2bfloat16_rn(x1 - __bfloat162float(h1));
    __nv_bfloat162 H = __nv_bfloat162(h0, h1);
    __nv_bfloat162 L = __nv_bfloat162(l0, l1);
    wh = *reinterpret_cast<uint32_t*>(&H);
    wl = *reinterpret_cast<uint32_t*>(&L);
}

__device__ __forceinline__ void mma_bf16(float* d, const uint32_t* a, const uint32_t* b) {
    asm volatile(
        "mma.sync.aligned.m16n8k16.row.col.f32.bf16.bf16.f32 "
        "{%0,%1,%2,%3}, {%4,%5,%6,%7}, {%8,%9}, {%0,%1,%2,%3};"
        : "+f"(d[0]), "+f"(d[1]), "+f"(d[2]), "+f"(d[3])
        : "r"(a[0]), "r"(a[1]), "r"(a[2]), "r"(a[3]),
          "r"(b[0]), "r"(b[1]));
}

__device__ __forceinline__ float sigm(float x) { return 1.f/(1.f + expf(-x)); }

// ---------------- 3xBF16 GEMM (128x64 tile) with register prefetch ----------
// C = A[M,K] @ W[N,K]^T + bias. ACT: 0 none, 1 relu.
template<int ACT>
__global__ void __launch_bounds__(256)
gemm_bf16x3(const float* __restrict__ A, int lda,
            const float* __restrict__ W,
            const float* __restrict__ bias,
            float* __restrict__ C, int ldc, int K)
{
    __shared__ uint32_t AsH[128][20];
    __shared__ uint32_t AsL[128][20];
    __shared__ uint32_t WsH[64][20];
    __shared__ uint32_t WsL[64][20];

    const int tid   = threadIdx.x;
    const int warp  = tid >> 5;
    const int lane  = tid & 31;
    const int group = lane >> 2;
    const int tig   = lane & 3;
    const int wm    = warp >> 1;
    const int wn    = warp & 1;
    const int m0    = blockIdx.y * 128;
    const int n0    = blockIdx.x * 64;
    const int ra    = tid >> 3;        // loader row base
    const int c4    = (tid & 7) << 2;  // loader float col

    float acc[2][4][4];
    #pragma unroll
    for (int mi = 0; mi < 2; mi++)
        #pragma unroll
        for (int ni = 0; ni < 4; ni++)
            #pragma unroll
            for (int j = 0; j < 4; j++) acc[mi][ni][j] = 0.f;

    const int ntiles = K >> 5;
    float4 av[4], wv[2];

    // preload tile 0
    #pragma unroll
    for (int i = 0; i < 4; i++)
        av[i] = *(const float4*)(A + (size_t)(m0 + ra + i*32) * lda + c4);
    #pragma unroll
    for (int i = 0; i < 2; i++)
        wv[i] = *(const float4*)(W + (size_t)(n0 + ra + i*32) * K + c4);

    for (int t = 0; t < ntiles; t++) {
        // stage current tile into smem
        #pragma unroll
        for (int i = 0; i < 4; i++) {
            int r = ra + i*32, w = c4 >> 1;
            uint32_t h0, l0, h1, l1;
            split2(av[i].x, av[i].y, h0, l0);
            split2(av[i].z, av[i].w, h1, l1);
            AsH[r][w] = h0; AsH[r][w+1] = h1;
            AsL[r][w] = l0; AsL[r][w+1] = l1;
        }
        #pragma unroll
        for (int i = 0; i < 2; i++) {
            int r = ra + i*32, w = c4 >> 1;
            uint32_t h0, l0, h1, l1;
            split2(wv[i].x, wv[i].y, h0, l0);
            split2(wv[i].z, wv[i].w, h1, l1);
            WsH[r][w] = h0; WsH[r][w+1] = h1;
            WsL[r][w] = l0; WsL[r][w+1] = l1;
        }
        __syncthreads();

        // prefetch next tile while MMAs run
        if (t + 1 < ntiles) {
            int k0 = (t + 1) << 5;
            #pragma unroll
            for (int i = 0; i < 4; i++)
                av[i] = *(const float4*)(A + (size_t)(m0 + ra + i*32) * lda + k0 + c4);
            #pragma unroll
            for (int i = 0; i < 2; i++)
                wv[i] = *(const float4*)(W + (size_t)(n0 + ra + i*32) * K + k0 + c4);
        }

        #pragma unroll
        for (int kk = 0; kk < 2; kk++) {
            const int w0 = kk * 8 + tig;
            const int w1 = w0 + 4;
            uint32_t aH[2][4], aL[2][4];
            #pragma unroll
            for (int mi = 0; mi < 2; mi++) {
                int row = wm * 32 + mi * 16 + group;
                aH[mi][0] = AsH[row][w0];     aL[mi][0] = AsL[row][w0];
                aH[mi][1] = AsH[row + 8][w0]; aL[mi][1] = AsL[row + 8][w0];
                aH[mi][2] = AsH[row][w1];     aL[mi][2] = AsL[row][w1];
                aH[mi][3] = AsH[row + 8][w1]; aL[mi][3] = AsL[row + 8][w1];
            }
            uint32_t bH[4][2], bL[4][2];
            #pragma unroll
            for (int ni = 0; ni < 4; ni++) {
                int rn = wn * 32 + ni * 8 + group;
                bH[ni][0] = WsH[rn][w0]; bL[ni][0] = WsL[rn][w0];
                bH[ni][1] = WsH[rn][w1]; bL[ni][1] = WsL[rn][w1];
            }
            #pragma unroll
            for (int mi = 0; mi < 2; mi++)
                #pragma unroll
                for (int ni = 0; ni < 4; ni++) {
                    mma_bf16(acc[mi][ni], aH[mi], bL[ni]);
                    mma_bf16(acc[mi][ni], aL[mi], bH[ni]);
                    mma_bf16(acc[mi][ni], aH[mi], bH[ni]);
                }
        }
        __syncthreads();
    }

    #pragma unroll
    for (int mi = 0; mi < 2; mi++) {
        #pragma unroll
        for (int ni = 0; ni < 4; ni++) {
            int row = m0 + wm * 32 + mi * 16 + group;
            int col = n0 + wn * 32 + ni * 8 + 2 * tig;
            float b0 = bias[col], b1 = bias[col + 1];
            float v0 = acc[mi][ni][0] + b0;
            float v1 = acc[mi][ni][1] + b1;
            float v2 = acc[mi][ni][2] + b0;
            float v3 = acc[mi][ni][3] + b1;
            if (ACT == 1) {
                v0 = fmaxf(v0, 0.f); v1 = fmaxf(v1, 0.f);
                v2 = fmaxf(v2, 0.f); v3 = fmaxf(v3, 0.f);
            }
            *(float2*)(C + (size_t)row * ldc + col)       = make_float2(v0, v1);
            *(float2*)(C + (size_t)(row + 8) * ldc + col) = make_float2(v2, v3);
        }
    }
}

// ---------------- fused gh-GEMM + GRU ---------------------------------------
// BM=64 rows, BN=192 = 3 gates x 64 h-cols (n0h = blockIdx.x*64).
// gh = hidden @ W_hh^T; stage tile in smem; epilogue does GRU with GI + h_in,
// writes h to CC[:, :256] and hout. 256 threads, 8 warps (2m x 4n, tile 32x48).
#define STG_STRIDE 196
__global__ void __launch_bounds__(256)
gru_fused(const float* __restrict__ hidden, const float* __restrict__ Whh,
          const float* __restrict__ bhh, const float* __restrict__ GI,
          float* __restrict__ cc, float* __restrict__ hout)
{
    extern __shared__ uint32_t dynsm[];
    uint32_t (*AsH)[20] = (uint32_t(*)[20])dynsm;                    // [64][20]
    uint32_t (*AsL)[20] = (uint32_t(*)[20])(dynsm + 64*20);
    uint32_t (*WsH)[20] = (uint32_t(*)[20])(dynsm + 2*64*20);        // [192][20]
    uint32_t (*WsL)[20] = (uint32_t(*)[20])(dynsm + 2*64*20 + 192*20);
    float*   stage      = (float*)dynsm;                             // [64][196]

    const int tid   = threadIdx.x;
    const int warp  = tid >> 5;
    const int lane  = tid & 31;
    const int group = lane >> 2;
    const int tig   = lane & 3;
    const int wm    = warp >> 2;       // 0..1
    const int wn    = warp & 3;        // 0..3
    const int m0    = blockIdx.y * 64;
    const int n0h   = blockIdx.x * 64; // h-col block
    const int ra    = tid >> 3;
    const int c4    = (tid & 7) << 2;

    float acc[2][6][4];
    #pragma unroll
    for (int mi = 0; mi < 2; mi++)
        #pragma unroll
        for (int ni = 0; ni < 6; ni++)
            #pragma unroll
            for (int j = 0; j < 4; j++) acc[mi][ni][j] = 0.f;

    for (int k0 = 0; k0 < 256; k0 += 32) {
        #pragma unroll
        for (int i = 0; i < 2; i++) {          // A: 64x32
            int r = ra + i*32, w = c4 >> 1;
            float4 v = *(const float4*)(hidden + (size_t)(m0 + r) * 256 + k0 + c4);
            uint32_t h0, l0, h1, l1;
            split2(v.x, v.y, h0, l0);
            split2(v.z, v.w, h1, l1);
            AsH[r][w] = h0; AsH[r][w+1] = h1;
            AsL[r][w] = l0; AsL[r][w+1] = l1;
        }
        #pragma unroll
        for (int i = 0; i < 6; i++) {          // W: 192x32, row j -> Whh[(j/64)*256 + n0h + j%64]
            int r = ra + i*32, w = c4 >> 1;
            int wr = (r >> 6) * 256 + n0h + (r & 63);
            float4 v = *(const float4*)(Whh + (size_t)wr * 256 + k0 + c4);
            uint32_t h0, l0, h1, l1;
            split2(v.x, v.y, h0, l0);
            split2(v.z, v.w, h1, l1);
            WsH[r][w] = h0; WsH[r][w+1] = h1;
            WsL[r][w] = l0; WsL[r][w+1] = l1;
        }
        __syncthreads();

        #pragma unroll
        for (int kk = 0; kk < 2; kk++) {
            const int w0 = kk * 8 + tig;
            const int w1 = w0 + 4;
            uint32_t aH[2][4], aL[2][4];
            #pragma unroll
            for (int mi = 0; mi < 2; mi++) {
                int row = wm * 32 + mi * 16 + group;
                aH[mi][0] = AsH[row][w0];     aL[mi][0] = AsL[row][w0];
                aH[mi][1] = AsH[row + 8][w0]; aL[mi][1] = AsL[row + 8][w0];
                aH[mi][2] = AsH[row][w1];     aL[mi][2] = AsL[row][w1];
                aH[mi][3] = AsH[row + 8][w1]; aL[mi][3] = AsL[row + 8][w1];
            }
            uint32_t bH[6][2], bL[6][2];
            #pragma unroll
            for (int ni = 0; ni < 6; ni++) {
                int rn = wn * 48 + ni * 8 + group;
                bH[ni][0] = WsH[rn][w0]; bL[ni][0] = WsL[rn][w0];
                bH[ni][1] = WsH[rn][w1]; bL[ni][1] = WsL[rn][w1];
            }
            #pragma unroll
            for (int mi = 0; mi < 2; mi++)
                #pragma unroll
                for (int ni = 0; ni < 6; ni++) {
                    mma_bf16(acc[mi][ni], aH[mi], bL[ni]);
                    mma_bf16(acc[mi][ni], aL[mi], bH[ni]);
                    mma_bf16(acc[mi][ni], aH[mi], bH[ni]);
                }
        }
        __syncthreads();
    }

    // stage gh tile (64 x 192) in smem (aliases operand smem)
    #pragma unroll
    for (int mi = 0; mi < 2; mi++) {
        #pragma unroll
        for (int ni = 0; ni < 6; ni++) {
            int row = wm * 32 + mi * 16 + group;
            int col = wn * 48 + ni * 8 + 2 * tig;
            stage[row * STG_STRIDE + col]           = acc[mi][ni][0];
            stage[row * STG_STRIDE + col + 1]       = acc[mi][ni][1];
            stage[(row + 8) * STG_STRIDE + col]     = acc[mi][ni][2];
            stage[(row + 8) * STG_STRIDE + col + 1] = acc[mi][ni][3];
        }
    }
    __syncthreads();

    // GRU epilogue: 64x64 h values, 16 per thread
    #pragma unroll
    for (int j = 0; j < 16; j++) {
        int e = tid + j * 256;
        int row = e >> 6, hcol = e & 63;
        int grow = m0 + row;
        int gcol = n0h + hcol;
        float ghr = stage[row * STG_STRIDE + hcol]       + bhh[gcol];
        float ghz = stage[row * STG_STRIDE + 64 + hcol]  + bhh[256 + gcol];
        float ghn = stage[row * STG_STRIDE + 128 + hcol] + bhh[512 + gcol];
        const float* gi = GI + (size_t)grow * 768 + gcol;
        float gir = gi[0], giz = gi[256], gin = gi[512];
        float hin = hidden[(size_t)grow * 256 + gcol];
        float r = sigm(gir + ghr);
        float z = sigm(giz + ghz);
        float n = tanhf(gin + r * ghn);
        float h = (1.f - z) * n + z * hin;
        cc[(size_t)grow * CCW + gcol] = h;
        if (hout) hout[(size_t)grow * 256 + gcol] = h;
    }
}

// ---------------- fused q/k/v GEMM (BN=192 via 3 weight ptrs) ---------------
__global__ void __launch_bounds__(256)
qkv_fused(const float* __restrict__ CC,
          const float* __restrict__ qw, const float* __restrict__ qb,
          const float* __restrict__ kw, const float* __restrict__ kb,
          const float* __restrict__ vw, const float* __restrict__ vb,
          float* __restrict__ Q, float* __restrict__ K, float* __restrict__ V)
{
    __shared__ uint32_t AsH[64][20];
    __shared__ uint32_t AsL[64][20];
    __shared__ uint32_t WsH[192][20];
    __shared__ uint32_t WsL[192][20];

    const int tid   = threadIdx.x;
    const int warp  = tid >> 5;
    const int lane  = tid & 31;
    const int group = lane >> 2;
    const int tig   = lane & 3;
    const int wm    = warp >> 2;
    const int wn    = warp & 3;
    const int m0    = blockIdx.y * 64;
    const int ra    = tid >> 3;
    const int c4    = (tid & 7) << 2;

    float acc[2][6][4];
    #pragma unroll
    for (int mi = 0; mi < 2; mi++)
        #pragma unroll
        for (int ni = 0; ni < 6; ni++)
            #pragma unroll
            for (int j = 0; j < 4; j++) acc[mi][ni][j] = 0.f;

    for (int k0 = 0; k0 < 256; k0 += 32) {
        #pragma unroll
        for (int i = 0; i < 2; i++) {
            int r = ra + i*32, w = c4 >> 1;
            float4 v = *(const float4*)(CC + (size_t)(m0 + r) * CCW + k0 + c4);
            uint32_t h0, l0, h1, l1;
            split2(v.x, v.y, h0, l0);
            split2(v.z, v.w, h1, l1);
            AsH[r][w] = h0; AsH[r][w+1] = h1;
            AsL[r][w] = l0; AsL[r][w+1] = l1;
        }
        #pragma unroll
        for (int i = 0; i < 6; i++) {
            int r = ra + i*32, w = c4 >> 1;
            const float* wp = (r < 64) ? (qw + (size_t)r * 256)
                             : (r < 128) ? (kw + (size_t)(r - 64) * 256)
                                         : (vw + (size_t)(r - 128) * 256);
            float4 v = *(const float4*)(wp + k0 + c4);
            uint32_t h0, l0, h1, l1;
            split2(v.x, v.y, h0, l0);
            split2(v.z, v.w, h1, l1);
            WsH[r][w] = h0; WsH[r][w+1] = h1;
            WsL[r][w] = l0; WsL[r][w+1] = l1;
        }
        __syncthreads();

        #pragma unroll
        for (int kk = 0; kk < 2; kk++) {
            const int w0 = kk * 8 + tig;
            const int w1 = w0 + 4;
            uint32_t aH[2][4], aL[2][4];
            #pragma unroll
            for (int mi = 0; mi < 2; mi++) {
                int row = wm * 32 + mi * 16 + group;
                aH[mi][0] = AsH[row][w0];     aL[mi][0] = AsL[row][w0];
                aH[mi][1] = AsH[row + 8][w0]; aL[mi][1] = AsL[row + 8][w0];
                aH[mi][2] = AsH[row][w1];     aL[mi][2] = AsL[row][w1];
                aH[mi][3] = AsH[row + 8][w1]; aL[mi][3] = AsL[row + 8][w1];
            }
            uint32_t bH[6][2], bL[6][2];
            #pragma unroll
            for (int ni = 0; ni < 6; ni++) {
                int rn = wn * 48 + ni * 8 + group;
                bH[ni][0] = WsH[rn][w0]; bL[ni][0] = WsL[rn][w0];
                bH[ni][1] = WsH[rn][w1]; bL[ni][1] = WsL[rn][w1];
            }
            #pragma unroll
            for (int mi = 0; mi < 2; mi++)
                #pragma unroll
                for (int ni = 0; ni < 6; ni++) {
                    mma_bf16(acc[mi][ni], aH[mi], bL[ni]);
                    mma_bf16(acc[mi][ni], aL[mi], bH[ni]);
                    mma_bf16(acc[mi][ni], aH[mi], bH[ni]);
                }
        }
        __syncthreads();
    }

    #pragma unroll
    for (int mi = 0; mi < 2; mi++) {
        #pragma unroll
        for (int ni = 0; ni < 6; ni++) {
            int row = m0 + wm * 32 + mi * 16 + group;
            int col = wn * 48 + ni * 8 + 2 * tig;       // 0..191, frag within one output
            float* dst; const float* bs; int oc;
            if (col < 64)       { dst = Q; bs = qb; oc = col; }
            else if (col < 128) { dst = K; bs = kb; oc = col - 64; }
            else                { dst = V; bs = vb; oc = col - 128; }
            float b0 = bs[oc], b1 = bs[oc + 1];
            *(float2*)(dst + (size_t)row * 64 + oc) =
                make_float2(acc[mi][ni][0] + b0, acc[mi][ni][1] + b1);
            *(float2*)(dst + (size_t)(row + 8) * 64 + oc) =
                make_float2(acc[mi][ni][2] + b0, acc[mi][ni][3] + b1);
        }
    }
}

// ---------------- head gates ------------------------------------------------
__global__ void __launch_bounds__(256)
gate_kernel(const float* __restrict__ CC, const float* __restrict__ gw,
            const float* __restrict__ gb, float* __restrict__ gate)
{
    int gwp  = (int)(((size_t)blockIdx.x*blockDim.x + threadIdx.x) >> 5);
    int lane = threadIdx.x & 31;
    if (gwp >= ROWS) return;
    int o = lane >> 3, part = lane & 7;
    const float* hr = CC + (size_t)gwp*CCW;
    const float* wr = gw + o*256;
    float s = 0.f;
    for (int k = part*4; k < 256; k += 32) {
        float4 hv = *(const float4*)(hr + k);
        float4 wv = *(const float4*)(wr + k);
        s += hv.x*wv.x + hv.y*wv.y + hv.z*wv.z + hv.w*wv.w;
    }
    s += __shfl_down_sync(0xffffffffu, s, 4, 8);
    s += __shfl_down_sync(0xffffffffu, s, 2, 8);
    s += __shfl_down_sync(0xffffffffu, s, 1, 8);
    if (part == 0) gate[(size_t)gwp*NHEAD + o] = sigm(s + gb[o]);
}

// ---------------- per-batch sparse attention --------------------------------
__global__ void __launch_bounds__(256)
attn_kernel(const float* __restrict__ Q, const float* __restrict__ K,
            const float* __restrict__ V, const float* __restrict__ gate,
            float* __restrict__ cc)
{
    __shared__ float QS[32][65], KS[32][65], VS[32][65];
    __shared__ float SS[4][32][33];
    const int b   = blockIdx.x;
    const int tid = threadIdx.x;
    const float* Qb = Q + (size_t)b*2048;
    const float* Kb = K + (size_t)b*2048;
    const float* Vb = V + (size_t)b*2048;

    for (int i = tid; i < 2048; i += 256) {
        int r = i >> 6, c = i & 63;
        QS[r][c] = Qb[i]; KS[r][c] = Kb[i]; VS[r][c] = Vb[i];
    }
    __syncthreads();

    for (int i = tid; i < 4096; i += 256) {
        int q = i >> 7, rem = i & 127;
        int h = rem >> 5, k = rem & 31;
        float s;
        if (q == k) s = NEGV;
        else {
            float acc = 0.f;
            #pragma unroll
            for (int d = 0; d < 16; d++) acc += QS[q][h*16+d]*KS[k][h*16+d];
            s = 0.25f*acc;
        }
        SS[h][q][k] = s;
    }
    __syncthreads();

    if (tid < 128) {
        int h = tid >> 5, q = tid & 31;
        float v[32];
        #pragma unroll
        for (int k = 0; k < 32; k++) v[k] = SS[h][q][k];
        float maxv = -INFINITY;
        unsigned keep = 0u;
        #pragma unroll
        for (int k = 0; k < 32; k++) {
            int cnt = 0;
            #pragma unroll
            for (int j = 0; j < 32; j++) cnt += (v[j] > v[k]);
            if (cnt < TOPKN) { keep |= (1u << k); maxv = fmaxf(maxv, v[k]); }
        }
        float e[32], sum = 0.f;
        #pragma unroll
        for (int k = 0; k < 32; k++) {
            float ek = ((keep >> k) & 1u) ? expf(v[k] - maxv) : 0.f;
            e[k] = ek; sum += ek;
        }
        float inv = 1.f / sum;
        #pragma unroll
        for (int k = 0; k < 32; k++) SS[h][q][k] = e[k]*inv;
    }
    __syncthreads();

    for (int i = tid; i < 2048; i += 256) {
        int q = i >> 6, hv = i & 63, h = hv >> 4;
        float acc = 0.f;
        #pragma unroll
        for (int k = 0; k < 32; k++) acc += SS[h][q][k]*VS[k][hv];
        float gt = gate[((size_t)b*32 + q)*NHEAD + h];
        cc[((size_t)b*32 + q)*CCW + 256 + hv] = acc*gt;
    }
}

// ---------------- p2 head ---------------------------------------------------
__global__ void __launch_bounds__(256)
p2_kernel(const float* __restrict__ P1, const float* __restrict__ w,
          const float* __restrict__ b, float* __restrict__ out)
{
    __shared__ float WS[20*257];
    int tid = threadIdx.x;
    for (int i = tid; i < 20*256; i += 256) {
        int o = i >> 8, k = i & 255;
        WS[o*257 + k] = w[i];
    }
    __syncthreads();
    int r = tid / 20, o = tid % 20;
    int row = blockIdx.x*12 + r;
    if (tid >= 240 || row >= ROWS) return;
    const float* a  = P1 + (size_t)row*256;
    const float* wr = WS + o*257;
    float s = b[o];
    #pragma unroll 4
    for (int k = 0; k < 256; k += 4) {
        float4 av = *(const float4*)(a + k);
        s += av.x*wr[k] + av.y*wr[k+1] + av.z*wr[k+2] + av.w*wr[k+3];
    }
    out[(size_t)row*NACT + o] = s;
}

// ---------------------------------------------------------------------------
extern "C" void kernel_launch(void* const* d_in, const int* in_sizes, int n_in,
                              void* d_out, int out_size)
{
    const float* inputs = (const float*)d_in[0];
    const float* hidden = (const float*)d_in[1];
    const float* fc1_w  = (const float*)d_in[2];
    const float* fc1_b  = (const float*)d_in[3];
    const float* w_ih   = (const float*)d_in[4];
    const float* w_hh   = (const float*)d_in[5];
    const float* b_ih   = (const float*)d_in[6];
    const float* b_hh   = (const float*)d_in[7];
    const float* q_w    = (const float*)d_in[8];
    const float* q_b    = (const float*)d_in[9];
    const float* k_w    = (const float*)d_in[10];
    const float* k_b    = (const float*)d_in[11];
    const float* v_w    = (const float*)d_in[12];
    const float* v_b    = (const float*)d_in[13];
    const float* g_w    = (const float*)d_in[14];
    const float* g_b    = (const float*)d_in[15];
    const float* p1_w   = (const float*)d_in[16];
    const float* p1_b   = (const float*)d_in[17];
    const float* p2_w   = (const float*)d_in[18];
    const float* p2_b   = (const float*)d_in[19];

    float *X, *GI, *CC, *Q, *K, *V, *GT, *P1;
    cudaGetSymbolAddress((void**)&X,  g_X);
    cudaGetSymbolAddress((void**)&GI, g_GI);
    cudaGetSymbolAddress((void**)&CC, g_CC);
    cudaGetSymbolAddress((void**)&Q,  g_Q);
    cudaGetSymbolAddress((void**)&K,  g_K);
    cudaGetSymbolAddress((void**)&V,  g_V);
    cudaGetSymbolAddress((void**)&GT, g_GT);
    cudaGetSymbolAddress((void**)&P1, g_P1);

    float* out  = (float*)d_out;
    float* hout = nullptr;
    long long need = (long long)ROWS*NACT + (long long)ROWS*HIDN;
    if ((long long)out_size >= need) hout = out + (size_t)ROWS*NACT;

    static int smem_set = 0;
    if (!smem_set) {
        cudaFuncSetAttribute(gru_fused, cudaFuncAttributeMaxDynamicSharedMemorySize, 64*STG_STRIDE*4);
        smem_set = 1;
    }

    dim3 thr(256);

    // 1) x = relu(inputs @ fc1_w^T + fc1_b)
    gemm_bf16x3<1><<<dim3(4, ROWS/128), thr>>>(inputs, 256, fc1_w, fc1_b, X, 256, 256);
    // 2) gi = x @ W_ih^T + b_ih
    gemm_bf16x3<0><<<dim3(12, ROWS/128), thr>>>(X, 256, w_ih, b_ih, GI, 768, 256);
    // 3) fused gh GEMM + GRU -> h into CC[:, :256] and hout
    gru_fused<<<dim3(4, ROWS/64), thr, 64*STG_STRIDE*4>>>(hidden, w_hh, b_hh, GI, CC, hout);
    // 4) fused q/k/v projections
    qkv_fused<<<dim3(1, ROWS/64), thr>>>(CC, q_w, q_b, k_w, k_b, v_w, v_b, Q, K, V);
    // 5) head gates
    gate_kernel<<<(ROWS*32)/256, 256>>>(CC, g_w, g_b, GT);
    // 6) sparse top-8 attention -> CC[:, 256:320]
    attn_kernel<<<BSZ, 256>>>(Q, K, V, GT, CC);
    // 7) p1 = relu(CC @ p1_w^T + p1_b)
    gemm_bf16x3<1><<<dim3(4, ROWS/128), thr>>>(CC, CCW, p1_w, p1_b, P1, 256, 320);
    // 8) logits = p1 @ p2_w^T + p2_b
    p2_kernel<<<(ROWS + 11)/12, 256>>>(P1, p2_w, p2_b, out);
}

// round 6
// speedup vs baseline: 2.3429x; 1.1450x over previous
#include <cuda_runtime.h>
#include <cuda_bf16.h>
#include <math.h>
#include <stdint.h>

#define BSZ    2048
#define A_N    32
#define ROWS   (BSZ*A_N)        // 65536
#define HIDN   256
#define NHEAD  4
#define TOPKN  8
#define NACT   20
#define NEGV   (-1e10f)
#define CCW    320

// ---------------- scratch ---------------------------------------------------
__device__ float g_X [(size_t)ROWS*HIDN];
__device__ float g_GI[(size_t)ROWS*3*HIDN];
__device__ float g_CC[(size_t)ROWS*CCW];
__device__ float g_Q [(size_t)ROWS*64];
__device__ float g_K [(size_t)ROWS*64];
__device__ float g_V [(size_t)ROWS*64];
__device__ float g_GT[(size_t)ROWS*NHEAD];
__device__ float g_P1[(size_t)ROWS*HIDN];

// ---------------- helpers ---------------------------------------------------
__device__ __forceinline__ void split2(float x0, float x1, uint32_t& wh, uint32_t& wl) {
    __nv_bfloat16 h0 = __float2bfloat16_rn(x0);
    __nv_bfloat16 h1 = __float2bfloat16_rn(x1);
    __nv_bfloat16 l0 = __float2bfloat16_rn(x0 - __bfloat162float(h0));
    __nv_bfloat16 l1 = __float2bfloat16_rn(x1 - __bfloat162float(h1));
    __nv_bfloat162 H = __nv_bfloat162(h0, h1);
    __nv_bfloat162 L = __nv_bfloat162(l0, l1);
    wh = *reinterpret_cast<uint32_t*>(&H);
    wl = *reinterpret_cast<uint32_t*>(&L);
}

__device__ __forceinline__ void mma_bf16(float* d, const uint32_t* a, const uint32_t* b) {
    asm volatile(
        "mma.sync.aligned.m16n8k16.row.col.f32.bf16.bf16.f32 "
        "{%0,%1,%2,%3}, {%4,%5,%6,%7}, {%8,%9}, {%0,%1,%2,%3};"
        : "+f"(d[0]), "+f"(d[1]), "+f"(d[2]), "+f"(d[3])
        : "r"(a[0]), "r"(a[1]), "r"(a[2]), "r"(a[3]),
          "r"(b[0]), "r"(b[1]));
}

__device__ __forceinline__ void ldsm_x4(uint32_t& r0, uint32_t& r1, uint32_t& r2, uint32_t& r3,
                                        uint32_t addr) {
    asm volatile("ldmatrix.sync.aligned.m8n8.x4.shared.b16 {%0,%1,%2,%3}, [%4];"
        : "=r"(r0), "=r"(r1), "=r"(r2), "=r"(r3) : "r"(addr));
}

__device__ __forceinline__ float sigm(float x) { return 1.f/(1.f + expf(-x)); }

// ================= generic GEMM: C = A[M,K] @ W[N,K]^T + bias ===============
// 128x64 CTA tile, 8 warps (warp 32x32), BK=32, 2-stage smem, ldmatrix frags.
#define G_AH 0
#define G_AL (128*20)
#define G_WH (256*20)
#define G_WL (320*20)
#define GSW  (384*20)      // words per stage

template<int ACT>
__global__ void __launch_bounds__(256,2)
gemm_bf16x3(const float* __restrict__ A, int lda,
            const float* __restrict__ W,
            const float* __restrict__ bias,
            float* __restrict__ C, int ldc, int K)
{
    extern __shared__ uint32_t sm[];
    const int tid   = threadIdx.x;
    const int warp  = tid >> 5;
    const int lane  = tid & 31;
    const int group = lane >> 2;
    const int tig   = lane & 3;
    const int wm    = warp >> 1;
    const int wn    = warp & 1;
    const int m0    = blockIdx.y * 128;
    const int n0    = blockIdx.x * 64;
    const int ra    = tid >> 3;
    const int c4    = (tid & 7) << 2;
    const int wc    = c4 >> 1;

    // ldmatrix lane-source offsets
    const int arow = (lane & 7) + ((lane >> 3) & 1) * 8;   // + wm*32 + mi*16
    const int awh  = ((lane >> 4) & 1) * 4;
    const int brow = (lane & 7) + ((lane >> 4) & 1) * 8;   // + wn*32 + j*16
    const int bwh  = ((lane >> 3) & 1) * 4;
    const uint32_t smb = (uint32_t)__cvta_generic_to_shared(sm);

    float acc[2][4][4];
    #pragma unroll
    for (int mi = 0; mi < 2; mi++)
        #pragma unroll
        for (int ni = 0; ni < 4; ni++)
            #pragma unroll
            for (int j = 0; j < 4; j++) acc[mi][ni][j] = 0.f;

    const int ntiles = K >> 5;
    float4 av[4], wv[2];
    #pragma unroll
    for (int i = 0; i < 4; i++)
        av[i] = *(const float4*)(A + (size_t)(m0 + ra + i*32) * lda + c4);
    #pragma unroll
    for (int i = 0; i < 2; i++)
        wv[i] = *(const float4*)(W + (size_t)(n0 + ra + i*32) * K + c4);

    // stage 0 STS
    {
        #pragma unroll
        for (int i = 0; i < 4; i++) {
            int r = ra + i*32;
            uint32_t h0,l0,h1,l1;
            split2(av[i].x, av[i].y, h0, l0);
            split2(av[i].z, av[i].w, h1, l1);
            sm[G_AH + r*20 + wc] = h0; sm[G_AH + r*20 + wc+1] = h1;
            sm[G_AL + r*20 + wc] = l0; sm[G_AL + r*20 + wc+1] = l1;
        }
        #pragma unroll
        for (int i = 0; i < 2; i++) {
            int r = ra + i*32;
            uint32_t h0,l0,h1,l1;
            split2(wv[i].x, wv[i].y, h0, l0);
            split2(wv[i].z, wv[i].w, h1, l1);
            sm[G_WH + r*20 + wc] = h0; sm[G_WH + r*20 + wc+1] = h1;
            sm[G_WL + r*20 + wc] = l0; sm[G_WL + r*20 + wc+1] = l1;
        }
    }
    __syncthreads();

    for (int t = 0; t < ntiles; t++) {
        const int sb = (t & 1) * GSW;
        if (t + 1 < ntiles) {
            int k0 = (t + 1) << 5;
            #pragma unroll
            for (int i = 0; i < 4; i++)
                av[i] = *(const float4*)(A + (size_t)(m0 + ra + i*32) * lda + k0 + c4);
            #pragma unroll
            for (int i = 0; i < 2; i++)
                wv[i] = *(const float4*)(W + (size_t)(n0 + ra + i*32) * K + k0 + c4);
        }

        #pragma unroll
        for (int kk = 0; kk < 2; kk++) {
            uint32_t aH[2][4], aL[2][4];
            #pragma unroll
            for (int mi = 0; mi < 2; mi++) {
                int r = wm*32 + mi*16 + arow;
                uint32_t ad = smb + ((sb + G_AH + r*20 + kk*8 + awh) << 2);
                ldsm_x4(aH[mi][0], aH[mi][1], aH[mi][2], aH[mi][3], ad);
                ldsm_x4(aL[mi][0], aL[mi][1], aL[mi][2], aL[mi][3], ad + ((G_AL - G_AH) << 2));
            }
            #pragma unroll
            for (int j = 0; j < 2; j++) {
                int r = wn*32 + j*16 + brow;
                uint32_t bd = smb + ((sb + G_WH + r*20 + kk*8 + bwh) << 2);
                uint32_t bH[2][2], bL[2][2];
                ldsm_x4(bH[0][0], bH[0][1], bH[1][0], bH[1][1], bd);
                ldsm_x4(bL[0][0], bL[0][1], bL[1][0], bL[1][1], bd + ((G_WL - G_WH) << 2));
                #pragma unroll
                for (int mi = 0; mi < 2; mi++)
                    #pragma unroll
                    for (int p = 0; p < 2; p++) {
                        int ni = 2*j + p;
                        mma_bf16(acc[mi][ni], aH[mi], bL[p]);
                        mma_bf16(acc[mi][ni], aL[mi], bH[p]);
                        mma_bf16(acc[mi][ni], aH[mi], bH[p]);
                    }
            }
        }

        if (t + 1 < ntiles) {
            const int nb = ((t + 1) & 1) * GSW;
            #pragma unroll
            for (int i = 0; i < 4; i++) {
                int r = ra + i*32;
                uint32_t h0,l0,h1,l1;
                split2(av[i].x, av[i].y, h0, l0);
                split2(av[i].z, av[i].w, h1, l1);
                sm[nb + G_AH + r*20 + wc] = h0; sm[nb + G_AH + r*20 + wc+1] = h1;
                sm[nb + G_AL + r*20 + wc] = l0; sm[nb + G_AL + r*20 + wc+1] = l1;
            }
            #pragma unroll
            for (int i = 0; i < 2; i++) {
                int r = ra + i*32;
                uint32_t h0,l0,h1,l1;
                split2(wv[i].x, wv[i].y, h0, l0);
                split2(wv[i].z, wv[i].w, h1, l1);
                sm[nb + G_WH + r*20 + wc] = h0; sm[nb + G_WH + r*20 + wc+1] = h1;
                sm[nb + G_WL + r*20 + wc] = l0; sm[nb + G_WL + r*20 + wc+1] = l1;
            }
        }
        __syncthreads();
    }

    #pragma unroll
    for (int mi = 0; mi < 2; mi++) {
        #pragma unroll
        for (int ni = 0; ni < 4; ni++) {
            int row = m0 + wm*32 + mi*16 + group;
            int col = n0 + wn*32 + ni*8 + 2*tig;
            float b0 = bias[col], b1 = bias[col+1];
            float v0 = acc[mi][ni][0] + b0;
            float v1 = acc[mi][ni][1] + b1;
            float v2 = acc[mi][ni][2] + b0;
            float v3 = acc[mi][ni][3] + b1;
            if (ACT == 1) {
                v0 = fmaxf(v0, 0.f); v1 = fmaxf(v1, 0.f);
                v2 = fmaxf(v2, 0.f); v3 = fmaxf(v3, 0.f);
            }
            *(float2*)(C + (size_t)row * ldc + col)       = make_float2(v0, v1);
            *(float2*)(C + (size_t)(row+8) * ldc + col)   = make_float2(v2, v3);
        }
    }
}

// ================= fused kernels: 64 x 192 tile ============================
#define F_AH 0
#define F_AL (64*20)
#define F_WH (128*20)
#define F_WL (320*20)
#define FSW  (512*20)      // words per stage (64*2 + 192*2 = 512 rows)
#define STG_STRIDE 196

// fused gh-GEMM + GRU
__global__ void __launch_bounds__(256,2)
gru_fused(const float* __restrict__ hidden, const float* __restrict__ Whh,
          const float* __restrict__ bhh, const float* __restrict__ GI,
          float* __restrict__ cc, float* __restrict__ hout)
{
    extern __shared__ uint32_t sm[];
    float* stage = (float*)sm;

    const int tid   = threadIdx.x;
    const int warp  = tid >> 5;
    const int lane  = tid & 31;
    const int group = lane >> 2;
    const int tig   = lane & 3;
    const int wm    = warp >> 2;       // 0..1
    const int wn    = warp & 3;        // 0..3
    const int m0    = blockIdx.y * 64;
    const int n0h   = blockIdx.x * 64;
    const int ra    = tid >> 3;
    const int c4    = (tid & 7) << 2;
    const int wc    = c4 >> 1;

    const int arow = (lane & 7) + ((lane >> 3) & 1) * 8;
    const int awh  = ((lane >> 4) & 1) * 4;
    const int brow = (lane & 7) + ((lane >> 4) & 1) * 8;
    const int bwh  = ((lane >> 3) & 1) * 4;
    const uint32_t smb = (uint32_t)__cvta_generic_to_shared(sm);

    float acc[2][6][4];
    #pragma unroll
    for (int mi = 0; mi < 2; mi++)
        #pragma unroll
        for (int ni = 0; ni < 6; ni++)
            #pragma unroll
            for (int j = 0; j < 4; j++) acc[mi][ni][j] = 0.f;

    float4 av[2], wv[6];
    #pragma unroll
    for (int i = 0; i < 2; i++)
        av[i] = *(const float4*)(hidden + (size_t)(m0 + ra + i*32) * 256 + c4);
    #pragma unroll
    for (int i = 0; i < 6; i++) {
        int r = ra + i*32;
        int wr = (r >> 6) * 256 + n0h + (r & 63);
        wv[i] = *(const float4*)(Whh + (size_t)wr * 256 + c4);
    }
    {
        #pragma unroll
        for (int i = 0; i < 2; i++) {
            int r = ra + i*32;
            uint32_t h0,l0,h1,l1;
            split2(av[i].x, av[i].y, h0, l0);
            split2(av[i].z, av[i].w, h1, l1);
            sm[F_AH + r*20 + wc] = h0; sm[F_AH + r*20 + wc+1] = h1;
            sm[F_AL + r*20 + wc] = l0; sm[F_AL + r*20 + wc+1] = l1;
        }
        #pragma unroll
        for (int i = 0; i < 6; i++) {
            int r = ra + i*32;
            uint32_t h0,l0,h1,l1;
            split2(wv[i].x, wv[i].y, h0, l0);
            split2(wv[i].z, wv[i].w, h1, l1);
            sm[F_WH + r*20 + wc] = h0; sm[F_WH + r*20 + wc+1] = h1;
            sm[F_WL + r*20 + wc] = l0; sm[F_WL + r*20 + wc+1] = l1;
        }
    }
    __syncthreads();

    for (int t = 0; t < 8; t++) {
        const int sb = (t & 1) * FSW;
        if (t + 1 < 8) {
            int k0 = (t + 1) << 5;
            #pragma unroll
            for (int i = 0; i < 2; i++)
                av[i] = *(const float4*)(hidden + (size_t)(m0 + ra + i*32) * 256 + k0 + c4);
            #pragma unroll
            for (int i = 0; i < 6; i++) {
                int r = ra + i*32;
                int wr = (r >> 6) * 256 + n0h + (r & 63);
                wv[i] = *(const float4*)(Whh + (size_t)wr * 256 + k0 + c4);
            }
        }

        #pragma unroll
        for (int kk = 0; kk < 2; kk++) {
            uint32_t aH[2][4], aL[2][4];
            #pragma unroll
            for (int mi = 0; mi < 2; mi++) {
                int r = wm*32 + mi*16 + arow;
                uint32_t ad = smb + ((sb + F_AH + r*20 + kk*8 + awh) << 2);
                ldsm_x4(aH[mi][0], aH[mi][1], aH[mi][2], aH[mi][3], ad);
                ldsm_x4(aL[mi][0], aL[mi][1], aL[mi][2], aL[mi][3], ad + ((F_AL - F_AH) << 2));
            }
            #pragma unroll
            for (int j = 0; j < 3; j++) {
                int r = wn*48 + j*16 + brow;
                uint32_t bd = smb + ((sb + F_WH + r*20 + kk*8 + bwh) << 2);
                uint32_t bH[2][2], bL[2][2];
                ldsm_x4(bH[0][0], bH[0][1], bH[1][0], bH[1][1], bd);
                ldsm_x4(bL[0][0], bL[0][1], bL[1][0], bL[1][1], bd + ((F_WL - F_WH) << 2));
                #pragma unroll
                for (int mi = 0; mi < 2; mi++)
                    #pragma unroll
                    for (int p = 0; p < 2; p++) {
                        int ni = 2*j + p;
                        mma_bf16(acc[mi][ni], aH[mi], bL[p]);
                        mma_bf16(acc[mi][ni], aL[mi], bH[p]);
                        mma_bf16(acc[mi][ni], aH[mi], bH[p]);
                    }
            }
        }

        if (t + 1 < 8) {
            const int nb = ((t + 1) & 1) * FSW;
            #pragma unroll
            for (int i = 0; i < 2; i++) {
                int r = ra + i*32;
                uint32_t h0,l0,h1,l1;
                split2(av[i].x, av[i].y, h0, l0);
                split2(av[i].z, av[i].w, h1, l1);
                sm[nb + F_AH + r*20 + wc] = h0; sm[nb + F_AH + r*20 + wc+1] = h1;
                sm[nb + F_AL + r*20 + wc] = l0; sm[nb + F_AL + r*20 + wc+1] = l1;
            }
            #pragma unroll
            for (int i = 0; i < 6; i++) {
                int r = ra + i*32;
                uint32_t h0,l0,h1,l1;
                split2(wv[i].x, wv[i].y, h0, l0);
                split2(wv[i].z, wv[i].w, h1, l1);
                sm[nb + F_WH + r*20 + wc] = h0; sm[nb + F_WH + r*20 + wc+1] = h1;
                sm[nb + F_WL + r*20 + wc] = l0; sm[nb + F_WL + r*20 + wc+1] = l1;
            }
        }
        __syncthreads();
    }

    // stage gh tile (64 x 192)
    #pragma unroll
    for (int mi = 0; mi < 2; mi++) {
        #pragma unroll
        for (int ni = 0; ni < 6; ni++) {
            int row = wm*32 + mi*16 + group;
            int col = wn*48 + ni*8 + 2*tig;
            stage[row * STG_STRIDE + col]           = acc[mi][ni][0];
            stage[row * STG_STRIDE + col + 1]       = acc[mi][ni][1];
            stage[(row+8) * STG_STRIDE + col]       = acc[mi][ni][2];
            stage[(row+8) * STG_STRIDE + col + 1]   = acc[mi][ni][3];
        }
    }
    __syncthreads();

    #pragma unroll
    for (int j = 0; j < 16; j++) {
        int e = tid + j * 256;
        int row = e >> 6, hcol = e & 63;
        int grow = m0 + row;
        int gcol = n0h + hcol;
        float ghr = stage[row * STG_STRIDE + hcol]       + bhh[gcol];
        float ghz = stage[row * STG_STRIDE + 64 + hcol]  + bhh[256 + gcol];
        float ghn = stage[row * STG_STRIDE + 128 + hcol] + bhh[512 + gcol];
        const float* gi = GI + (size_t)grow * 768 + gcol;
        float gir = gi[0], giz = gi[256], gin = gi[512];
        float hin = hidden[(size_t)grow * 256 + gcol];
        float r = sigm(gir + ghr);
        float z = sigm(giz + ghz);
        float n = tanhf(gin + r * ghn);
        float h = (1.f - z) * n + z * hin;
        cc[(size_t)grow * CCW + gcol] = h;
        if (hout) hout[(size_t)grow * 256 + gcol] = h;
    }
}

// fused q/k/v GEMM
__global__ void __launch_bounds__(256,2)
qkv_fused(const float* __restrict__ CC,
          const float* __restrict__ qw, const float* __restrict__ qb,
          const float* __restrict__ kw, const float* __restrict__ kb,
          const float* __restrict__ vw, const float* __restrict__ vb,
          float* __restrict__ Q, float* __restrict__ K, float* __restrict__ V)
{
    extern __shared__ uint32_t sm[];
    const int tid   = threadIdx.x;
    const int warp  = tid >> 5;
    const int lane  = tid & 31;
    const int group = lane >> 2;
    const int tig   = lane & 3;
    const int wm    = warp >> 2;
    const int wn    = warp & 3;
    const int m0    = blockIdx.y * 64;
    const int ra    = tid >> 3;
    const int c4    = (tid & 7) << 2;
    const int wc    = c4 >> 1;

    const int arow = (lane & 7) + ((lane >> 3) & 1) * 8;
    const int awh  = ((lane >> 4) & 1) * 4;
    const int brow = (lane & 7) + ((lane >> 4) & 1) * 8;
    const int bwh  = ((lane >> 3) & 1) * 4;
    const uint32_t smb = (uint32_t)__cvta_generic_to_shared(sm);

    float acc[2][6][4];
    #pragma unroll
    for (int mi = 0; mi < 2; mi++)
        #pragma unroll
        for (int ni = 0; ni < 6; ni++)
            #pragma unroll
            for (int j = 0; j < 4; j++) acc[mi][ni][j] = 0.f;

    float4 av[2], wv[6];
    #pragma unroll
    for (int i = 0; i < 2; i++)
        av[i] = *(const float4*)(CC + (size_t)(m0 + ra + i*32) * CCW + c4);
    #pragma unroll
    for (int i = 0; i < 6; i++) {
        int r = ra + i*32;
        const float* wp = (r < 64) ? (qw + (size_t)r * 256)
                         : (r < 128) ? (kw + (size_t)(r - 64) * 256)
                                     : (vw + (size_t)(r - 128) * 256);
        wv[i] = *(const float4*)(wp + c4);
    }
    {
        #pragma unroll
        for (int i = 0; i < 2; i++) {
            int r = ra + i*32;
            uint32_t h0,l0,h1,l1;
            split2(av[i].x, av[i].y, h0, l0);
            split2(av[i].z, av[i].w, h1, l1);
            sm[F_AH + r*20 + wc] = h0; sm[F_AH + r*20 + wc+1] = h1;
            sm[F_AL + r*20 + wc] = l0; sm[F_AL + r*20 + wc+1] = l1;
        }
        #pragma unroll
        for (int i = 0; i < 6; i++) {
            int r = ra + i*32;
            uint32_t h0,l0,h1,l1;
            split2(wv[i].x, wv[i].y, h0, l0);
            split2(wv[i].z, wv[i].w, h1, l1);
            sm[F_WH + r*20 + wc] = h0; sm[F_WH + r*20 + wc+1] = h1;
            sm[F_WL + r*20 + wc] = l0; sm[F_WL + r*20 + wc+1] = l1;
        }
    }
    __syncthreads();

    for (int t = 0; t < 8; t++) {
        const int sb = (t & 1) * FSW;
        if (t + 1 < 8) {
            int k0 = (t + 1) << 5;
            #pragma unroll
            for (int i = 0; i < 2; i++)
                av[i] = *(const float4*)(CC + (size_t)(m0 + ra + i*32) * CCW + k0 + c4);
            #pragma unroll
            for (int i = 0; i < 6; i++) {
                int r = ra + i*32;
                const float* wp = (r < 64) ? (qw + (size_t)r * 256)
                                 : (r < 128) ? (kw + (size_t)(r - 64) * 256)
                                             : (vw + (size_t)(r - 128) * 256);
                wv[i] = *(const float4*)(wp + k0 + c4);
            }
        }

        #pragma unroll
        for (int kk = 0; kk < 2; kk++) {
            uint32_t aH[2][4], aL[2][4];
            #pragma unroll
            for (int mi = 0; mi < 2; mi++) {
                int r = wm*32 + mi*16 + arow;
                uint32_t ad = smb + ((sb + F_AH + r*20 + kk*8 + awh) << 2);
                ldsm_x4(aH[mi][0], aH[mi][1], aH[mi][2], aH[mi][3], ad);
                ldsm_x4(aL[mi][0], aL[mi][1], aL[mi][2], aL[mi][3], ad + ((F_AL - F_AH) << 2));
            }
            #pragma unroll
            for (int j = 0; j < 3; j++) {
                int r = wn*48 + j*16 + brow;
                uint32_t bd = smb + ((sb + F_WH + r*20 + kk*8 + bwh) << 2);
                uint32_t bH[2][2], bL[2][2];
                ldsm_x4(bH[0][0], bH[0][1], bH[1][0], bH[1][1], bd);
                ldsm_x4(bL[0][0], bL[0][1], bL[1][0], bL[1][1], bd + ((F_WL - F_WH) << 2));
                #pragma unroll
                for (int mi = 0; mi < 2; mi++)
                    #pragma unroll
                    for (int p = 0; p < 2; p++) {
                        int ni = 2*j + p;
                        mma_bf16(acc[mi][ni], aH[mi], bL[p]);
                        mma_bf16(acc[mi][ni], aL[mi], bH[p]);
                        mma_bf16(acc[mi][ni], aH[mi], bH[p]);
                    }
            }
        }

        if (t + 1 < 8) {
            const int nb = ((t + 1) & 1) * FSW;
            #pragma unroll
            for (int i = 0; i < 2; i++) {
                int r = ra + i*32;
                uint32_t h0,l0,h1,l1;
                split2(av[i].x, av[i].y, h0, l0);
                split2(av[i].z, av[i].w, h1, l1);
                sm[nb + F_AH + r*20 + wc] = h0; sm[nb + F_AH + r*20 + wc+1] = h1;
                sm[nb + F_AL + r*20 + wc] = l0; sm[nb + F_AL + r*20 + wc+1] = l1;
            }
            #pragma unroll
            for (int i = 0; i < 6; i++) {
                int r = ra + i*32;
                uint32_t h0,l0,h1,l1;
                split2(wv[i].x, wv[i].y, h0, l0);
                split2(wv[i].z, wv[i].w, h1, l1);
                sm[nb + F_WH + r*20 + wc] = h0; sm[nb + F_WH + r*20 + wc+1] = h1;
                sm[nb + F_WL + r*20 + wc] = l0; sm[nb + F_WL + r*20 + wc+1] = l1;
            }
        }
        __syncthreads();
    }

    #pragma unroll
    for (int mi = 0; mi < 2; mi++) {
        #pragma unroll
        for (int ni = 0; ni < 6; ni++) {
            int row = m0 + wm*32 + mi*16 + group;
            int col = wn*48 + ni*8 + 2*tig;
            float* dst; const float* bs; int oc;
            if (col < 64)       { dst = Q; bs = qb; oc = col; }
            else if (col < 128) { dst = K; bs = kb; oc = col - 64; }
            else                { dst = V; bs = vb; oc = col - 128; }
            float b0 = bs[oc], b1 = bs[oc+1];
            *(float2*)(dst + (size_t)row * 64 + oc) =
                make_float2(acc[mi][ni][0] + b0, acc[mi][ni][1] + b1);
            *(float2*)(dst + (size_t)(row+8) * 64 + oc) =
                make_float2(acc[mi][ni][2] + b0, acc[mi][ni][3] + b1);
        }
    }
}

// ---------------- head gates ------------------------------------------------
__global__ void __launch_bounds__(256)
gate_kernel(const float* __restrict__ CC, const float* __restrict__ gw,
            const float* __restrict__ gb, float* __restrict__ gate)
{
    int gwp  = (int)(((size_t)blockIdx.x*blockDim.x + threadIdx.x) >> 5);
    int lane = threadIdx.x & 31;
    if (gwp >= ROWS) return;
    int o = lane >> 3, part = lane & 7;
    const float* hr = CC + (size_t)gwp*CCW;
    const float* wr = gw + o*256;
    float s = 0.f;
    for (int k = part*4; k < 256; k += 32) {
        float4 hv = *(const float4*)(hr + k);
        float4 wv = *(const float4*)(wr + k);
        s += hv.x*wv.x + hv.y*wv.y + hv.z*wv.z + hv.w*wv.w;
    }
    s += __shfl_down_sync(0xffffffffu, s, 4, 8);
    s += __shfl_down_sync(0xffffffffu, s, 2, 8);
    s += __shfl_down_sync(0xffffffffu, s, 1, 8);
    if (part == 0) gate[(size_t)gwp*NHEAD + o] = sigm(s + gb[o]);
}

// ---------------- per-batch sparse attention --------------------------------
__global__ void __launch_bounds__(256)
attn_kernel(const float* __restrict__ Q, const float* __restrict__ K,
            const float* __restrict__ V, const float* __restrict__ gate,
            float* __restrict__ cc)
{
    __shared__ float QS[32][65], KS[32][65], VS[32][65];
    __shared__ float SS[4][32][33];
    const int b   = blockIdx.x;
    const int tid = threadIdx.x;
    const float* Qb = Q + (size_t)b*2048;
    const float* Kb = K + (size_t)b*2048;
    const float* Vb = V + (size_t)b*2048;

    for (int i = tid; i < 2048; i += 256) {
        int r = i >> 6, c = i & 63;
        QS[r][c] = Qb[i]; KS[r][c] = Kb[i]; VS[r][c] = Vb[i];
    }
    __syncthreads();

    for (int i = tid; i < 4096; i += 256) {
        int q = i >> 7, rem = i & 127;
        int h = rem >> 5, k = rem & 31;
        float s;
        if (q == k) s = NEGV;
        else {
            float acc = 0.f;
            #pragma unroll
            for (int d = 0; d < 16; d++) acc += QS[q][h*16+d]*KS[k][h*16+d];
            s = 0.25f*acc;
        }
        SS[h][q][k] = s;
    }
    __syncthreads();

    if (tid < 128) {
        int h = tid >> 5, q = tid & 31;
        float v[32];
        #pragma unroll
        for (int k = 0; k < 32; k++) v[k] = SS[h][q][k];
        float maxv = -INFINITY;
        unsigned keep = 0u;
        #pragma unroll
        for (int k = 0; k < 32; k++) {
            int cnt = 0;
            #pragma unroll
            for (int j = 0; j < 32; j++) cnt += (v[j] > v[k]);
            if (cnt < TOPKN) { keep |= (1u << k); maxv = fmaxf(maxv, v[k]); }
        }
        float e[32], sum = 0.f;
        #pragma unroll
        for (int k = 0; k < 32; k++) {
            float ek = ((keep >> k) & 1u) ? expf(v[k] - maxv) : 0.f;
            e[k] = ek; sum += ek;
        }
        float inv = 1.f / sum;
        #pragma unroll
        for (int k = 0; k < 32; k++) SS[h][q][k] = e[k]*inv;
    }
    __syncthreads();

    for (int i = tid; i < 2048; i += 256) {
        int q = i >> 6, hv = i & 63, h = hv >> 4;
        float acc = 0.f;
        #pragma unroll
        for (int k = 0; k < 32; k++) acc += SS[h][q][k]*VS[k][hv];
        float gt = gate[((size_t)b*32 + q)*NHEAD + h];
        cc[((size_t)b*32 + q)*CCW + 256 + hv] = acc*gt;
    }
}

// ---------------- p2 head ---------------------------------------------------
__global__ void __launch_bounds__(256)
p2_kernel(const float* __restrict__ P1, const float* __restrict__ w,
          const float* __restrict__ b, float* __restrict__ out)
{
    __shared__ float WS[20*257];
    int tid = threadIdx.x;
    for (int i = tid; i < 20*256; i += 256) {
        int o = i >> 8, k = i & 255;
        WS[o*257 + k] = w[i];
    }
    __syncthreads();
    int r = tid / 20, o = tid % 20;
    int row = blockIdx.x*12 + r;
    if (tid >= 240 || row >= ROWS) return;
    const float* a  = P1 + (size_t)row*256;
    const float* wr = WS + o*257;
    float s = b[o];
    #pragma unroll 4
    for (int k = 0; k < 256; k += 4) {
        float4 av = *(const float4*)(a + k);
        s += av.x*wr[k] + av.y*wr[k+1] + av.z*wr[k+2] + av.w*wr[k+3];
    }
    out[(size_t)row*NACT + o] = s;
}

// ---------------------------------------------------------------------------
extern "C" void kernel_launch(void* const* d_in, const int* in_sizes, int n_in,
                              void* d_out, int out_size)
{
    const float* inputs = (const float*)d_in[0];
    const float* hidden = (const float*)d_in[1];
    const float* fc1_w  = (const float*)d_in[2];
    const float* fc1_b  = (const float*)d_in[3];
    const float* w_ih   = (const float*)d_in[4];
    const float* w_hh   = (const float*)d_in[5];
    const float* b_ih   = (const float*)d_in[6];
    const float* b_hh   = (const float*)d_in[7];
    const float* q_w    = (const float*)d_in[8];
    const float* q_b    = (const float*)d_in[9];
    const float* k_w    = (const float*)d_in[10];
    const float* k_b    = (const float*)d_in[11];
    const float* v_w    = (const float*)d_in[12];
    const float* v_b    = (const float*)d_in[13];
    const float* g_w    = (const float*)d_in[14];
    const float* g_b    = (const float*)d_in[15];
    const float* p1_w   = (const float*)d_in[16];
    const float* p1_b   = (const float*)d_in[17];
    const float* p2_w   = (const float*)d_in[18];
    const float* p2_b   = (const float*)d_in[19];

    float *X, *GI, *CC, *Q, *K, *V, *GT, *P1;
    cudaGetSymbolAddress((void**)&X,  g_X);
    cudaGetSymbolAddress((void**)&GI, g_GI);
    cudaGetSymbolAddress((void**)&CC, g_CC);
    cudaGetSymbolAddress((void**)&Q,  g_Q);
    cudaGetSymbolAddress((void**)&K,  g_K);
    cudaGetSymbolAddress((void**)&V,  g_V);
    cudaGetSymbolAddress((void**)&GT, g_GT);
    cudaGetSymbolAddress((void**)&P1, g_P1);

    float* out  = (float*)d_out;
    float* hout = nullptr;
    long long need = (long long)ROWS*NACT + (long long)ROWS*HIDN;
    if ((long long)out_size >= need) hout = out + (size_t)ROWS*NACT;

    const int gsm = 2 * GSW * 4;                 // 61440 B
    const int fsm = 2 * FSW * 4;                 // 81920 B
    static int smem_set = 0;
    if (!smem_set) {
        cudaFuncSetAttribute(gemm_bf16x3<0>, cudaFuncAttributeMaxDynamicSharedMemorySize, gsm);
        cudaFuncSetAttribute(gemm_bf16x3<1>, cudaFuncAttributeMaxDynamicSharedMemorySize, gsm);
        cudaFuncSetAttribute(gru_fused, cudaFuncAttributeMaxDynamicSharedMemorySize, fsm);
        cudaFuncSetAttribute(qkv_fused, cudaFuncAttributeMaxDynamicSharedMemorySize, fsm);
        smem_set = 1;
    }

    dim3 thr(256);

    gemm_bf16x3<1><<<dim3(4, ROWS/128), thr, gsm>>>(inputs, 256, fc1_w, fc1_b, X, 256, 256);
    gemm_bf16x3<0><<<dim3(12, ROWS/128), thr, gsm>>>(X, 256, w_ih, b_ih, GI, 768, 256);
    gru_fused<<<dim3(4, ROWS/64), thr, fsm>>>(hidden, w_hh, b_hh, GI, CC, hout);
    qkv_fused<<<dim3(1, ROWS/64), thr, fsm>>>(CC, q_w, q_b, k_w, k_b, v_w, v_b, Q, K, V);
    gate_kernel<<<(ROWS*32)/256, 256>>>(CC, g_w, g_b, GT);
    attn_kernel<<<BSZ, 256>>>(Q, K, V, GT, CC);
    gemm_bf16x3<1><<<dim3(4, ROWS/128), thr, gsm>>>(CC, CCW, p1_w, p1_b, P1, 256, 320);
    p2_kernel<<<(ROWS + 11)/12, 256>>>(P1, p2_w, p2_b, out);
}

// round 8
// speedup vs baseline: 2.4811x; 1.0590x over previous
#include <cuda_runtime.h>
#include <cuda_bf16.h>
#include <math.h>
#include <stdint.h>

#define BSZ    2048
#define A_N    32
#define ROWS   (BSZ*A_N)        // 65536
#define HIDN   256
#define NHEAD  4
#define TOPKN  8
#define NACT   20
#define NEGV   (-1e10f)
#define CCW    320

// ---------------- scratch ---------------------------------------------------
// blocked hi/lo bf16 layout: [row][K/32 blocks][hi x32 | lo x32], row stride 2K
__device__ __nv_bfloat16 g_InHL [(size_t)ROWS*512];
__device__ __nv_bfloat16 g_HidHL[(size_t)ROWS*512];
__device__ __nv_bfloat16 g_XHL  [(size_t)ROWS*512];
__device__ __nv_bfloat16 g_CCHL [(size_t)ROWS*640];
__device__ __nv_bfloat16 g_W1HL [256*512];
__device__ __nv_bfloat16 g_WiHL [768*512];
__device__ __nv_bfloat16 g_WhHL [768*512];
__device__ __nv_bfloat16 g_QKVHL[192*512];
__device__ __nv_bfloat16 g_P1WHL[256*640];
__device__ float g_GI[(size_t)ROWS*3*HIDN];
__device__ float g_Q [(size_t)ROWS*64];
__device__ float g_K [(size_t)ROWS*64];
__device__ float g_V [(size_t)ROWS*64];
__device__ float g_GT[(size_t)ROWS*NHEAD];
__device__ float g_P1[(size_t)ROWS*HIDN];

// ---------------- helpers ---------------------------------------------------
__device__ __forceinline__ void split2(float x0, float x1, uint32_t& wh, uint32_t& wl) {
    __nv_bfloat16 h0 = __float2bfloat16_rn(x0);
    __nv_bfloat16 h1 = __float2bfloat16_rn(x1);
    __nv_bfloat16 l0 = __float2bfloat16_rn(x0 - __bfloat162float(h0));
    __nv_bfloat16 l1 = __float2bfloat16_rn(x1 - __bfloat162float(h1));
    __nv_bfloat162 H = __nv_bfloat162(h0, h1);
    __nv_bfloat162 L = __nv_bfloat162(l0, l1);
    wh = *reinterpret_cast<uint32_t*>(&H);
    wl = *reinterpret_cast<uint32_t*>(&L);
}

__device__ __forceinline__ float2 rec2(uint32_t h, uint32_t l) {
    __nv_bfloat162 H = *reinterpret_cast<__nv_bfloat162*>(&h);
    __nv_bfloat162 L = *reinterpret_cast<__nv_bfloat162*>(&l);
    return make_float2(__bfloat162float(H.x) + __bfloat162float(L.x),
                       __bfloat162float(H.y) + __bfloat162float(L.y));
}

__device__ __forceinline__ void mma_bf16(float* d, const uint32_t* a, const uint32_t* b) {
    asm volatile(
        "mma.sync.aligned.m16n8k16.row.col.f32.bf16.bf16.f32 "
        "{%0,%1,%2,%3}, {%4,%5,%6,%7}, {%8,%9}, {%0,%1,%2,%3};"
        : "+f"(d[0]), "+f"(d[1]), "+f"(d[2]), "+f"(d[3])
        : "r"(a[0]), "r"(a[1]), "r"(a[2]), "r"(a[3]),
          "r"(b[0]), "r"(b[1]));
}

__device__ __forceinline__ void ldsm_x4(uint32_t& r0, uint32_t& r1, uint32_t& r2, uint32_t& r3,
                                        uint32_t addr) {
    asm volatile("ldmatrix.sync.aligned.m8n8.x4.shared.b16 {%0,%1,%2,%3}, [%4];"
        : "=r"(r0), "=r"(r1), "=r"(r2), "=r"(r3) : "r"(addr));
}

__device__ __forceinline__ void cp16(uint32_t dst, const void* src) {
    asm volatile("cp.async.cg.shared.global [%0], [%1], 16;" :: "r"(dst), "l"(src));
}
__device__ __forceinline__ void cp_commit() {
    asm volatile("cp.async.commit_group;" ::: "memory");
}
template<int N>
__device__ __forceinline__ void cp_wait() {
    asm volatile("cp.async.wait_group %0;" :: "n"(N) : "memory");
}

__device__ __forceinline__ float sigm(float x) { return 1.f/(1.f + expf(-x)); }

// swizzled smem byte offset for (row, 16B-chunk) within a 128B-row tile
__device__ __forceinline__ uint32_t swz(int row, int ch) {
    return (uint32_t)(row * 128 + ((ch ^ (row & 7)) << 4));
}

// ---------------- f32 -> blocked hi/lo bf16 ---------------------------------
__global__ void __launch_bounds__(256)
conv_blk(const float4* __restrict__ src, __nv_bfloat16* __restrict__ dst,
         int Kd4, int n4)
{
    int i = blockIdx.x * blockDim.x + threadIdx.x;
    if (i >= n4) return;
    int r = i / Kd4;
    int c4 = (i - r * Kd4) * 4;
    float4 v = src[i];
    uint32_t h0, l0, h1, l1;
    split2(v.x, v.y, h0, l0);
    split2(v.z, v.w, h1, l1);
    int b = c4 >> 5, pos = c4 & 31;
    __nv_bfloat16* base = dst + (size_t)r * (Kd4 * 8) + b * 64 + pos;
    *(uint32_t*)(base)      = h0; *(uint32_t*)(base + 2)  = h1;
    *(uint32_t*)(base + 32) = l0; *(uint32_t*)(base + 34) = l1;
}

// ================= generic GEMM: 128x64 tile, cp.async 3-stage ==============
// C = A[M,K] @ W[N,K]^T + bias; operands blocked hi/lo bf16.
#define GST_B 24576
#define GW_OFF 16384

template<int ACT, int OUTHL>
__global__ void __launch_bounds__(256,2)
gemmHL(const __nv_bfloat16* __restrict__ A, int as,
       const __nv_bfloat16* __restrict__ W, int ws,
       const float* __restrict__ bias,
       float* __restrict__ Cf, int ldc,
       __nv_bfloat16* __restrict__ Chl, int os,
       int ntiles)
{
    extern __shared__ char smc[];
    const uint32_t smb = (uint32_t)__cvta_generic_to_shared(smc);
    const int tid = threadIdx.x, lane = tid & 31, warp = tid >> 5;
    const int group = lane >> 2, tig = lane & 3;
    const int wm = warp >> 1, wn = warp & 1;
    const int m0 = blockIdx.y * 128, n0 = blockIdx.x * 64;

    const int arow = (lane & 7) + ((lane >> 3) & 1) * 8;
    const int akc  = (lane >> 4) & 1;
    const int brow = (lane & 7) + ((lane >> 4) & 1) * 8;
    const int bkc  = (lane >> 3) & 1;

    float acc[2][4][4];
    #pragma unroll
    for (int mi = 0; mi < 2; mi++)
        #pragma unroll
        for (int ni = 0; ni < 4; ni++)
            #pragma unroll
            for (int j = 0; j < 4; j++) acc[mi][ni][j] = 0.f;

    const int lrow = tid >> 3, lch = tid & 7;

    // issue stage t
    #define G_ISSUE(t) {                                                        \
        uint32_t sb_ = smb + ((t) % 3) * GST_B;                                 \
        _Pragma("unroll")                                                       \
        for (int i_ = 0; i_ < 4; i_++) {                                        \
            int row_ = lrow + i_ * 32;                                          \
            cp16(sb_ + swz(row_, lch),                                          \
                 A + (size_t)(m0 + row_) * as + (t) * 64 + lch * 8);            \
        }                                                                       \
        _Pragma("unroll")                                                       \
        for (int i_ = 0; i_ < 2; i_++) {                                        \
            int row_ = lrow + i_ * 32;                                          \
            cp16(sb_ + GW_OFF + swz(row_, lch),                                 \
                 W + (size_t)(n0 + row_) * ws + (t) * 64 + lch * 8);            \
        }                                                                       \
        cp_commit();                                                            \
    }

    G_ISSUE(0);
    if (ntiles > 1) G_ISSUE(1);

    for (int t = 0; t < ntiles; t++) {
        if (t + 1 < ntiles) cp_wait<1>(); else cp_wait<0>();
        __syncthreads();
        if (t + 2 < ntiles) G_ISSUE(t + 2);

        const uint32_t sb = smb + (t % 3) * GST_B;
        #pragma unroll
        for (int kk = 0; kk < 2; kk++) {
            uint32_t aH[2][4], aL[2][4];
            #pragma unroll
            for (int mi = 0; mi < 2; mi++) {
                int r = wm * 32 + mi * 16 + arow;
                int ch = 2 * kk + akc;
                ldsm_x4(aH[mi][0], aH[mi][1], aH[mi][2], aH[mi][3], sb + swz(r, ch));
                ldsm_x4(aL[mi][0], aL[mi][1], aL[mi][2], aL[mi][3], sb + swz(r, ch + 4));
            }
            #pragma unroll
            for (int j = 0; j < 2; j++) {
                int r = wn * 32 + j * 16 + brow;
                int ch = 2 * kk + bkc;
                uint32_t bH[2][2], bL[2][2];
                ldsm_x4(bH[0][0], bH[0][1], bH[1][0], bH[1][1], sb + GW_OFF + swz(r, ch));
                ldsm_x4(bL[0][0], bL[0][1], bL[1][0], bL[1][1], sb + GW_OFF + swz(r, ch + 4));
                #pragma unroll
                for (int mi = 0; mi < 2; mi++)
                    #pragma unroll
                    for (int p = 0; p < 2; p++) {
                        int ni = 2 * j + p;
                        mma_bf16(acc[mi][ni], aH[mi], bL[p]);
                        mma_bf16(acc[mi][ni], aL[mi], bH[p]);
                        mma_bf16(acc[mi][ni], aH[mi], bH[p]);
                    }
            }
        }
    }
    #undef G_ISSUE

    #pragma unroll
    for (int mi = 0; mi < 2; mi++) {
        #pragma unroll
        for (int ni = 0; ni < 4; ni++) {
            int row = m0 + wm * 32 + mi * 16 + group;
            int col = n0 + wn * 32 + ni * 8 + 2 * tig;
            float b0 = bias[col], b1 = bias[col + 1];
            float v0 = acc[mi][ni][0] + b0;
            float v1 = acc[mi][ni][1] + b1;
            float v2 = acc[mi][ni][2] + b0;
            float v3 = acc[mi][ni][3] + b1;
            if (ACT == 1) {
                v0 = fmaxf(v0, 0.f); v1 = fmaxf(v1, 0.f);
                v2 = fmaxf(v2, 0.f); v3 = fmaxf(v3, 0.f);
            }
            if (OUTHL == 0) {
                *(float2*)(Cf + (size_t)row * ldc + col)       = make_float2(v0, v1);
                *(float2*)(Cf + (size_t)(row + 8) * ldc + col) = make_float2(v2, v3);
            } else {
                int b = col >> 5, pos = col & 31;
                uint32_t h, l;
                split2(v0, v1, h, l);
                *(uint32_t*)(Chl + (size_t)row * os + b * 64 + pos)      = h;
                *(uint32_t*)(Chl + (size_t)row * os + b * 64 + 32 + pos) = l;
                split2(v2, v3, h, l);
                *(uint32_t*)(Chl + (size_t)(row + 8) * os + b * 64 + pos)      = h;
                *(uint32_t*)(Chl + (size_t)(row + 8) * os + b * 64 + 32 + pos) = l;
            }
        }
    }
}

// ================= fused 64x192 kernels ====================================
#define FST_B 32768
#define FW_OFF 8192
#define STG_STRIDE 196

// gh GEMM + GRU epilogue
__global__ void __launch_bounds__(256,2)
gru_fused(const __nv_bfloat16* __restrict__ HidHL, const __nv_bfloat16* __restrict__ WhHL,
          const float* __restrict__ hidden,
          const float* __restrict__ bhh, const float* __restrict__ GI,
          __nv_bfloat16* __restrict__ cchl, float* __restrict__ hout)
{
    extern __shared__ char smc[];
    const uint32_t smb = (uint32_t)__cvta_generic_to_shared(smc);
    float* stage = (float*)smc;

    const int tid = threadIdx.x, lane = tid & 31, warp = tid >> 5;
    const int group = lane >> 2, tig = lane & 3;
    const int wm = warp >> 2, wn = warp & 3;
    const int m0 = blockIdx.y * 64, n0h = blockIdx.x * 64;

    const int arow = (lane & 7) + ((lane >> 3) & 1) * 8;
    const int akc  = (lane >> 4) & 1;
    const int brow = (lane & 7) + ((lane >> 4) & 1) * 8;
    const int bkc  = (lane >> 3) & 1;
    const int lrow = tid >> 3, lch = tid & 7;

    float acc[2][6][4];
    #pragma unroll
    for (int mi = 0; mi < 2; mi++)
        #pragma unroll
        for (int ni = 0; ni < 6; ni++)
            #pragma unroll
            for (int j = 0; j < 4; j++) acc[mi][ni][j] = 0.f;

    #define F_ISSUE(t) {                                                        \
        uint32_t sb_ = smb + ((t) % 3) * FST_B;                                 \
        _Pragma("unroll")                                                       \
        for (int i_ = 0; i_ < 2; i_++) {                                        \
            int row_ = lrow + i_ * 32;                                          \
            cp16(sb_ + swz(row_, lch),                                          \
                 HidHL + (size_t)(m0 + row_) * 512 + (t) * 64 + lch * 8);       \
        }                                                                       \
        _Pragma("unroll")                                                       \
        for (int i_ = 0; i_ < 6; i_++) {                                        \
            int row_ = lrow + i_ * 32;                                          \
            int wr_ = (row_ >> 6) * 256 + n0h + (row_ & 63);                    \
            cp16(sb_ + FW_OFF + swz(row_, lch),                                 \
                 WhHL + (size_t)wr_ * 512 + (t) * 64 + lch * 8);                \
        }                                                                       \
        cp_commit();                                                            \
    }

    F_ISSUE(0); F_ISSUE(1);

    for (int t = 0; t < 8; t++) {
        if (t + 1 < 8) cp_wait<1>(); else cp_wait<0>();
        __syncthreads();
        if (t + 2 < 8) F_ISSUE(t + 2);

        const uint32_t sb = smb + (t % 3) * FST_B;
        #pragma unroll
        for (int kk = 0; kk < 2; kk++) {
            uint32_t aH[2][4], aL[2][4];
            #pragma unroll
            for (int mi = 0; mi < 2; mi++) {
                int r = wm * 32 + mi * 16 + arow;
                int ch = 2 * kk + akc;
                ldsm_x4(aH[mi][0], aH[mi][1], aH[mi][2], aH[mi][3], sb + swz(r, ch));
                ldsm_x4(aL[mi][0], aL[mi][1], aL[mi][2], aL[mi][3], sb + swz(r, ch + 4));
            }
            #pragma unroll
            for (int j = 0; j < 3; j++) {
                int r = wn * 48 + j * 16 + brow;
                int ch = 2 * kk + bkc;
                uint32_t bH[2][2], bL[2][2];
                ldsm_x4(bH[0][0], bH[0][1], bH[1][0], bH[1][1], sb + FW_OFF + swz(r, ch));
                ldsm_x4(bL[0][0], bL[0][1], bL[1][0], bL[1][1], sb + FW_OFF + swz(r, ch + 4));
                #pragma unroll
                for (int mi = 0; mi < 2; mi++)
                    #pragma unroll
                    for (int p = 0; p < 2; p++) {
                        int ni = 2 * j + p;
                        mma_bf16(acc[mi][ni], aH[mi], bL[p]);
                        mma_bf16(acc[mi][ni], aL[mi], bH[p]);
                        mma_bf16(acc[mi][ni], aH[mi], bH[p]);
                    }
            }
        }
    }
    #undef F_ISSUE
    __syncthreads();

    // stage gh (64 x 192) in smem
    #pragma unroll
    for (int mi = 0; mi < 2; mi++) {
        #pragma unroll
        for (int ni = 0; ni < 6; ni++) {
            int row = wm * 32 + mi * 16 + group;
            int col = wn * 48 + ni * 8 + 2 * tig;
            stage[row * STG_STRIDE + col]         = acc[mi][ni][0];
            stage[row * STG_STRIDE + col + 1]     = acc[mi][ni][1];
            stage[(row+8) * STG_STRIDE + col]     = acc[mi][ni][2];
            stage[(row+8) * STG_STRIDE + col + 1] = acc[mi][ni][3];
        }
    }
    __syncthreads();

    #pragma unroll
    for (int j = 0; j < 16; j++) {
        int e = tid + j * 256;
        int row = e >> 6, hcol = e & 63;
        int grow = m0 + row;
        int gcol = n0h + hcol;
        float ghr = stage[row * STG_STRIDE + hcol]       + bhh[gcol];
        float ghz = stage[row * STG_STRIDE + 64 + hcol]  + bhh[256 + gcol];
        float ghn = stage[row * STG_STRIDE + 128 + hcol] + bhh[512 + gcol];
        const float* gi = GI + (size_t)grow * 768 + gcol;
        float gir = gi[0], giz = gi[256], gin = gi[512];
        float hin = hidden[(size_t)grow * 256 + gcol];
        float r = sigm(gir + ghr);
        float z = sigm(giz + ghz);
        float n = tanhf(gin + r * ghn);
        float h = (1.f - z) * n + z * hin;
        // write h to CCHL (blocked hi/lo) and hout (f32)
        int b = gcol >> 5, pos = gcol & 31;
        __nv_bfloat16 hb = __float2bfloat16_rn(h);
        __nv_bfloat16 lb = __float2bfloat16_rn(h - __bfloat162float(hb));
        __nv_bfloat16* dp = cchl + (size_t)grow * 640 + b * 64 + pos;
        dp[0]  = hb;
        dp[32] = lb;
        if (hout) hout[(size_t)grow * 256 + gcol] = h;
    }
}

// fused q/k/v GEMM (weights pre-stacked in QKVHL[192][512])
__global__ void __launch_bounds__(256,2)
qkv_fused(const __nv_bfloat16* __restrict__ CChl, const __nv_bfloat16* __restrict__ QKVw,
          const float* __restrict__ qb, const float* __restrict__ kb,
          const float* __restrict__ vb,
          float* __restrict__ Q, float* __restrict__ K, float* __restrict__ V)
{
    extern __shared__ char smc[];
    const uint32_t smb = (uint32_t)__cvta_generic_to_shared(smc);

    const int tid = threadIdx.x, lane = tid & 31, warp = tid >> 5;
    const int group = lane >> 2, tig = lane & 3;
    const int wm = warp >> 2, wn = warp & 3;
    const int m0 = blockIdx.y * 64;

    const int arow = (lane & 7) + ((lane >> 3) & 1) * 8;
    const int akc  = (lane >> 4) & 1;
    const int brow = (lane & 7) + ((lane >> 4) & 1) * 8;
    const int bkc  = (lane >> 3) & 1;
    const int lrow = tid >> 3, lch = tid & 7;

    float acc[2][6][4];
    #pragma unroll
    for (int mi = 0; mi < 2; mi++)
        #pragma unroll
        for (int ni = 0; ni < 6; ni++)
            #pragma unroll
            for (int j = 0; j < 4; j++) acc[mi][ni][j] = 0.f;

    #define Q_ISSUE(t) {                                                        \
        uint32_t sb_ = smb + ((t) % 3) * FST_B;                                 \
        _Pragma("unroll")                                                       \
        for (int i_ = 0; i_ < 2; i_++) {                                        \
            int row_ = lrow + i_ * 32;                                          \
            cp16(sb_ + swz(row_, lch),                                          \
                 CChl + (size_t)(m0 + row_) * 640 + (t) * 64 + lch * 8);        \
        }                                                                       \
        _Pragma("unroll")                                                       \
        for (int i_ = 0; i_ < 6; i_++) {                                        \
            int row_ = lrow + i_ * 32;                                          \
            cp16(sb_ + FW_OFF + swz(row_, lch),                                 \
                 QKVw + (size_t)row_ * 512 + (t) * 64 + lch * 8);               \
        }                                                                       \
        cp_commit();                                                            \
    }

    Q_ISSUE(0); Q_ISSUE(1);

    for (int t = 0; t < 8; t++) {
        if (t + 1 < 8) cp_wait<1>(); else cp_wait<0>();
        __syncthreads();
        if (t + 2 < 8) Q_ISSUE(t + 2);

        const uint32_t sb = smb + (t % 3) * FST_B;
        #pragma unroll
        for (int kk = 0; kk < 2; kk++) {
            uint32_t aH[2][4], aL[2][4];
            #pragma unroll
            for (int mi = 0; mi < 2; mi++) {
                int r = wm * 32 + mi * 16 + arow;
                int ch = 2 * kk + akc;
                ldsm_x4(aH[mi][0], aH[mi][1], aH[mi][2], aH[mi][3], sb + swz(r, ch));
                ldsm_x4(aL[mi][0], aL[mi][1], aL[mi][2], aL[mi][3], sb + swz(r, ch + 4));
            }
            #pragma unroll
            for (int j = 0; j < 3; j++) {
                int r = wn * 48 + j * 16 + brow;
                int ch = 2 * kk + bkc;
                uint32_t bH[2][2], bL[2][2];
                ldsm_x4(bH[0][0], bH[0][1], bH[1][0], bH[1][1], sb + FW_OFF + swz(r, ch));
                ldsm_x4(bL[0][0], bL[0][1], bL[1][0], bL[1][1], sb + FW_OFF + swz(r, ch + 4));
                #pragma unroll
                for (int mi = 0; mi < 2; mi++)
                    #pragma unroll
                    for (int p = 0; p < 2; p++) {
                        int ni = 2 * j + p;
                        mma_bf16(acc[mi][ni], aH[mi], bL[p]);
                        mma_bf16(acc[mi][ni], aL[mi], bH[p]);
                        mma_bf16(acc[mi][ni], aH[mi], bH[p]);
                    }
            }
        }
    }
    #undef Q_ISSUE

    #pragma unroll
    for (int mi = 0; mi < 2; mi++) {
        #pragma unroll
        for (int ni = 0; ni < 6; ni++) {
            int row = m0 + wm * 32 + mi * 16 + group;
            int col = wn * 48 + ni * 8 + 2 * tig;
            float* dst; const float* bs; int oc;
            if (col < 64)       { dst = Q; bs = qb; oc = col; }
            else if (col < 128) { dst = K; bs = kb; oc = col - 64; }
            else                { dst = V; bs = vb; oc = col - 128; }
            float b0 = bs[oc], b1 = bs[oc + 1];
            *(float2*)(dst + (size_t)row * 64 + oc) =
                make_float2(acc[mi][ni][0] + b0, acc[mi][ni][1] + b1);
            *(float2*)(dst + (size_t)(row + 8) * 64 + oc) =
                make_float2(acc[mi][ni][2] + b0, acc[mi][ni][3] + b1);
        }
    }
}

// ---------------- head gates (reads hi/lo CC) --------------------------------
__global__ void __launch_bounds__(256)
gate_kernel(const __nv_bfloat16* __restrict__ CChl, const float* __restrict__ gw,
            const float* __restrict__ gb, float* __restrict__ gate)
{
    int gwp  = (int)(((size_t)blockIdx.x*blockDim.x + threadIdx.x) >> 5);
    int lane = threadIdx.x & 31;
    if (gwp >= ROWS) return;
    int o = lane >> 3, part = lane & 7;
    const __nv_bfloat16* hr = CChl + (size_t)gwp * 640;
    const float* wr = gw + o * 256;
    float s = 0.f;
    #pragma unroll
    for (int j = 0; j < 8; j++) {
        int k = part * 4 + 32 * j;
        uint32_t h0 = *(const uint32_t*)(hr + j * 64 + part * 4);
        uint32_t h1 = *(const uint32_t*)(hr + j * 64 + part * 4 + 2);
        uint32_t l0 = *(const uint32_t*)(hr + j * 64 + 32 + part * 4);
        uint32_t l1 = *(const uint32_t*)(hr + j * 64 + 32 + part * 4 + 2);
        float2 a = rec2(h0, l0), b = rec2(h1, l1);
        float4 wv = *(const float4*)(wr + k);
        s += a.x*wv.x + a.y*wv.y + b.x*wv.z + b.y*wv.w;
    }
    s += __shfl_down_sync(0xffffffffu, s, 4, 8);
    s += __shfl_down_sync(0xffffffffu, s, 2, 8);
    s += __shfl_down_sync(0xffffffffu, s, 1, 8);
    if (part == 0) gate[(size_t)gwp*NHEAD + o] = sigm(s + gb[o]);
}

// ---------------- per-batch sparse attention ---------------------------------
__global__ void __launch_bounds__(256)
attn_kernel(const float* __restrict__ Q, const float* __restrict__ K,
            const float* __restrict__ V, const float* __restrict__ gate,
            __nv_bfloat16* __restrict__ cchl)
{
    __shared__ float QS[32][65], KS[32][65], VS[32][65];
    __shared__ float SS[4][32][33];
    const int b   = blockIdx.x;
    const int tid = threadIdx.x;
    const float* Qb = Q + (size_t)b*2048;
    const float* Kb = K + (size_t)b*2048;
    const float* Vb = V + (size_t)b*2048;

    for (int i = tid; i < 2048; i += 256) {
        int r = i >> 6, c = i & 63;
        QS[r][c] = Qb[i]; KS[r][c] = Kb[i]; VS[r][c] = Vb[i];
    }
    __syncthreads();

    for (int i = tid; i < 4096; i += 256) {
        int q = i >> 7, rem = i & 127;
        int h = rem >> 5, k = rem & 31;
        float s;
        if (q == k) s = NEGV;
        else {
            float acc = 0.f;
            #pragma unroll
            for (int d = 0; d < 16; d++) acc += QS[q][h*16+d]*KS[k][h*16+d];
            s = 0.25f*acc;
        }
        SS[h][q][k] = s;
    }
    __syncthreads();

    if (tid < 128) {
        int h = tid >> 5, q = tid & 31;
        float v[32];
        #pragma unroll
        for (int k = 0; k < 32; k++) v[k] = SS[h][q][k];
        float maxv = -INFINITY;
        unsigned keep = 0u;
        #pragma unroll
        for (int k = 0; k < 32; k++) {
            int cnt = 0;
            #pragma unroll
            for (int j = 0; j < 32; j++) cnt += (v[j] > v[k]);
            if (cnt < TOPKN) { keep |= (1u << k); maxv = fmaxf(maxv, v[k]); }
        }
        float e[32], sum = 0.f;
        #pragma unroll
        for (int k = 0; k < 32; k++) {
            float ek = ((keep >> k) & 1u) ? expf(v[k] - maxv) : 0.f;
            e[k] = ek; sum += ek;
        }
        float inv = 1.f / sum;
        #pragma unroll
        for (int k = 0; k < 32; k++) SS[h][q][k] = e[k]*inv;
    }
    __syncthreads();

    for (int i = tid; i < 2048; i += 256) {
        int q = i >> 6, hv = i & 63, h = hv >> 4;
        float acc = 0.f;
        #pragma unroll
        for (int k = 0; k < 32; k++) acc += SS[h][q][k]*VS[k][hv];
        float gt = gate[((size_t)b*32 + q)*NHEAD + h];
        float g = acc * gt;
        int c = 256 + hv;
        int blk = c >> 5, pos = c & 31;
        __nv_bfloat16 hb = __float2bfloat16_rn(g);
        __nv_bfloat16 lb = __float2bfloat16_rn(g - __bfloat162float(hb));
        __nv_bfloat16* dp = cchl + ((size_t)b*32 + q) * 640 + blk * 64 + pos;
        dp[0]  = hb;
        dp[32] = lb;
    }
}

// ---------------- p2 head ---------------------------------------------------
__global__ void __launch_bounds__(256)
p2_kernel(const float* __restrict__ P1, const float* __restrict__ w,
          const float* __restrict__ b, float* __restrict__ out)
{
    __shared__ float WS[20*257];
    int tid = threadIdx.x;
    for (int i = tid; i < 20*256; i += 256) {
        int o = i >> 8, k = i & 255;
        WS[o*257 + k] = w[i];
    }
    __syncthreads();
    int r = tid / 20, o = tid % 20;
    int row = blockIdx.x*12 + r;
    if (tid >= 240 || row >= ROWS) return;
    const float* a  = P1 + (size_t)row*256;
    const float* wr = WS + o*257;
    float s = b[o];
    #pragma unroll 4
    for (int k = 0; k < 256; k += 4) {
        float4 av = *(const float4*)(a + k);
        s += av.x*wr[k] + av.y*wr[k+1] + av.z*wr[k+2] + av.w*wr[k+3];
    }
    out[(size_t)row*NACT + o] = s;
}

// ---------------------------------------------------------------------------
extern "C" void kernel_launch(void* const* d_in, const int* in_sizes, int n_in,
                              void* d_out, int out_size)
{
    const float* inputs = (const float*)d_in[0];
    const float* hidden = (const float*)d_in[1];
    const float* fc1_w  = (const float*)d_in[2];
    const float* fc1_b  = (const float*)d_in[3];
    const float* w_ih   = (const float*)d_in[4];
    const float* w_hh   = (const float*)d_in[5];
    const float* b_ih   = (const float*)d_in[6];
    const float* b_hh   = (const float*)d_in[7];
    const float* q_w    = (const float*)d_in[8];
    const float* q_b    = (const float*)d_in[9];
    const float* k_w    = (const float*)d_in[10];
    const float* k_b    = (const float*)d_in[11];
    const float* v_w    = (const float*)d_in[12];
    const float* v_b    = (const float*)d_in[13];
    const float* g_w    = (const float*)d_in[14];
    const float* g_b    = (const float*)d_in[15];
    const float* p1_w   = (const float*)d_in[16];
    const float* p1_b   = (const float*)d_in[17];
    const float* p2_w   = (const float*)d_in[18];
    const float* p2_b   = (const float*)d_in[19];

    float *GI, *Q, *K, *V, *GT, *P1;
    __nv_bfloat16 *InHL, *HidHL, *XHL, *CCHL, *W1HL, *WiHL, *WhHL, *QKVHL, *P1WHL;
    cudaGetSymbolAddress((void**)&GI, g_GI);
    cudaGetSymbolAddress((void**)&Q,  g_Q);
    cudaGetSymbolAddress((void**)&K,  g_K);
    cudaGetSymbolAddress((void**)&V,  g_V);
    cudaGetSymbolAddress((void**)&GT, g_GT);
    cudaGetSymbolAddress((void**)&P1, g_P1);
    cudaGetSymbolAddress((void**)&InHL,  g_InHL);
    cudaGetSymbolAddress((void**)&HidHL, g_HidHL);
    cudaGetSymbolAddress((void**)&XHL,   g_XHL);
    cudaGetSymbolAddress((void**)&CCHL,  g_CCHL);
    cudaGetSymbolAddress((void**)&W1HL,  g_W1HL);
    cudaGetSymbolAddress((void**)&WiHL,  g_WiHL);
    cudaGetSymbolAddress((void**)&WhHL,  g_WhHL);
    cudaGetSymbolAddress((void**)&QKVHL, g_QKVHL);
    cudaGetSymbolAddress((void**)&P1WHL, g_P1WHL);

    float* out  = (float*)d_out;
    float* hout = nullptr;
    long long need = (long long)ROWS*NACT + (long long)ROWS*HIDN;
    if ((long long)out_size >= need) hout = out + (size_t)ROWS*NACT;

    const int gsm = 3 * GST_B;   // 73728
    const int fsm = 3 * FST_B;   // 98304
    static int smem_set = 0;
    if (!smem_set) {
        cudaFuncSetAttribute(gemmHL<0,0>, cudaFuncAttributeMaxDynamicSharedMemorySize, gsm);
        cudaFuncSetAttribute(gemmHL<1,0>, cudaFuncAttributeMaxDynamicSharedMemorySize, gsm);
        cudaFuncSetAttribute(gemmHL<1,1>, cudaFuncAttributeMaxDynamicSharedMemorySize, gsm);
        cudaFuncSetAttribute(gru_fused, cudaFuncAttributeMaxDynamicSharedMemorySize, fsm);
        cudaFuncSetAttribute(qkv_fused, cudaFuncAttributeMaxDynamicSharedMemorySize, fsm);
        smem_set = 1;
    }

    dim3 thr(256);

    // 0) conversions to blocked hi/lo bf16
    conv_blk<<<(ROWS*64 + 255)/256, thr>>>((const float4*)inputs, InHL, 64, ROWS*64);
    conv_blk<<<(ROWS*64 + 255)/256, thr>>>((const float4*)hidden, HidHL, 64, ROWS*64);
    conv_blk<<<(256*64 + 255)/256, thr>>>((const float4*)fc1_w, W1HL, 64, 256*64);
    conv_blk<<<(768*64 + 255)/256, thr>>>((const float4*)w_ih, WiHL, 64, 768*64);
    conv_blk<<<(768*64 + 255)/256, thr>>>((const float4*)w_hh, WhHL, 64, 768*64);
    conv_blk<<<(64*64 + 255)/256, thr>>>((const float4*)q_w, QKVHL,            64, 64*64);
    conv_blk<<<(64*64 + 255)/256, thr>>>((const float4*)k_w, QKVHL + 64*512,   64, 64*64);
    conv_blk<<<(64*64 + 255)/256, thr>>>((const float4*)v_w, QKVHL + 128*512,  64, 64*64);
    conv_blk<<<(256*80 + 255)/256, thr>>>((const float4*)p1_w, P1WHL, 80, 256*80);

    // 1) x = relu(inputs @ fc1_w^T + fc1_b) -> XHL
    gemmHL<1,1><<<dim3(4, ROWS/128), thr, gsm>>>(InHL, 512, W1HL, 512, fc1_b,
                                                 nullptr, 0, XHL, 512, 8);
    // 2) gi = x @ W_ih^T + b_ih -> GI (f32)
    gemmHL<0,0><<<dim3(12, ROWS/128), thr, gsm>>>(XHL, 512, WiHL, 512, b_ih,
                                                  GI, 768, nullptr, 0, 8);
    // 3) fused gh GEMM + GRU -> CCHL[:, blocks 0-7] + hout
    gru_fused<<<dim3(4, ROWS/64), thr, fsm>>>(HidHL, WhHL, hidden, b_hh, GI, CCHL, hout);
    // 4) fused q/k/v projections
    qkv_fused<<<dim3(1, ROWS/64), thr, fsm>>>(CCHL, QKVHL, q_b, k_b, v_b, Q, K, V);
    // 5) head gates
    gate_kernel<<<(ROWS*32)/256, thr>>>(CCHL, g_w, g_b, GT);
    // 6) sparse top-8 attention -> CCHL blocks 8-9
    attn_kernel<<<BSZ, thr>>>(Q, K, V, GT, CCHL);
    // 7) p1 = relu(CC @ p1_w^T + p1_b) -> P1 (f32)
    gemmHL<1,0><<<dim3(4, ROWS/128), thr, gsm>>>(CCHL, 640, P1WHL, 640, p1_b,
                                                 P1, 256, nullptr, 0, 10);
    // 8) logits
    p2_kernel<<<(ROWS + 11)/12, thr>>>(P1, p2_w, p2_b, out);
}